// round 2
// baseline (speedup 1.0000x reference)
#include <cuda_runtime.h>
#include <mma.h>
#include <cstdint>

using namespace nvcuda;

#define BATCH   32
#define SEQ     577
#define EMBED   768
#define HEADS   12
#define HDIM    64
#define MROWS   (BATCH * SEQ)        // 18464
#define QKV_N   (3 * EMBED)          // 2304
#define ATT_SCALE 0.125f             // HDIM^-0.5

// ---------------- scratch (module-load allocated, no runtime allocs) -------
__device__ float g_Q[(size_t)BATCH * HEADS * SEQ * HDIM];   // [b,h,n,d], pre-scaled
__device__ float g_K[(size_t)BATCH * HEADS * SEQ * HDIM];
__device__ float g_V[(size_t)BATCH * HEADS * SEQ * HDIM];
__device__ float g_O[(size_t)MROWS * EMBED];                // attention out [b,n, h*64+d]

// ===========================================================================
// Kernel 1: QKV GEMM.  C[M=18464, N=2304] = X[M,768] @ Wqkv[768,2304]
// 64x64 block tile, 8 warps (4x2), wmma tf32 m16n16k8, BK=32.
// Epilogue scatters into g_Q/g_K/g_V with [B,H,N,Dh] layout; Q scaled.
// ===========================================================================
__global__ void __launch_bounds__(256) gemm_qkv_kernel(const float* __restrict__ X,
                                                       const float* __restrict__ W)
{
    __shared__ float As[64][40];   // tf32-in-float
    __shared__ float Bs[32][72];
    __shared__ float Cs[64][72];

    const int tid  = threadIdx.x;
    const int warp = tid >> 5;
    const int wm   = warp >> 1;     // 0..3
    const int wn   = warp & 1;      // 0..1
    const int m0   = blockIdx.y * 64;
    const int n0   = blockIdx.x * 64;

    wmma::fragment<wmma::accumulator, 16, 16, 8, float> acc[2];
    wmma::fill_fragment(acc[0], 0.0f);
    wmma::fill_fragment(acc[1], 0.0f);

    for (int k0 = 0; k0 < EMBED; k0 += 32) {
        // A tile: 64 x 32 -> 512 float4
        for (int i = tid; i < 512; i += 256) {
            int r  = i >> 3;
            int c4 = (i & 7) << 2;
            int gm = m0 + r;
            float4 v = make_float4(0.f, 0.f, 0.f, 0.f);
            if (gm < MROWS)
                v = *(const float4*)(X + (size_t)gm * EMBED + k0 + c4);
            As[r][c4 + 0] = wmma::__float_to_tf32(v.x);
            As[r][c4 + 1] = wmma::__float_to_tf32(v.y);
            As[r][c4 + 2] = wmma::__float_to_tf32(v.z);
            As[r][c4 + 3] = wmma::__float_to_tf32(v.w);
        }
        // B tile: 32 x 64 -> 512 float4 (no bounds needed: 768%32==0, 2304%64==0)
        for (int i = tid; i < 512; i += 256) {
            int r  = i >> 4;
            int c4 = (i & 15) << 2;
            float4 v = *(const float4*)(W + (size_t)(k0 + r) * QKV_N + n0 + c4);
            Bs[r][c4 + 0] = wmma::__float_to_tf32(v.x);
            Bs[r][c4 + 1] = wmma::__float_to_tf32(v.y);
            Bs[r][c4 + 2] = wmma::__float_to_tf32(v.z);
            Bs[r][c4 + 3] = wmma::__float_to_tf32(v.w);
        }
        __syncthreads();

        #pragma unroll
        for (int kk = 0; kk < 4; kk++) {
            wmma::fragment<wmma::matrix_a, 16, 16, 8, wmma::precision::tf32, wmma::row_major> a;
            wmma::load_matrix_sync(a, &As[wm * 16][kk * 8], 40);
            #pragma unroll
            for (int j = 0; j < 2; j++) {
                wmma::fragment<wmma::matrix_b, 16, 16, 8, wmma::precision::tf32, wmma::row_major> b;
                wmma::load_matrix_sync(b, &Bs[kk * 8][wn * 32 + j * 16], 72);
                wmma::mma_sync(acc[j], a, b, acc[j]);
            }
        }
        __syncthreads();
    }

    wmma::store_matrix_sync(&Cs[wm * 16][wn * 32],      acc[0], 72, wmma::mem_row_major);
    wmma::store_matrix_sync(&Cs[wm * 16][wn * 32 + 16], acc[1], 72, wmma::mem_row_major);
    __syncthreads();

    // scatter: column n = s*768 + h*64 + d  ->  g_{Q,K,V}[((b*H+h)*SEQ+tok)*64 + d]
    for (int i = tid; i < 4096; i += 256) {
        int r  = i >> 6;
        int c  = i & 63;
        int gm = m0 + r;
        if (gm >= MROWS) continue;
        int gn  = n0 + c;
        int b   = gm / SEQ;
        int tok = gm - b * SEQ;
        int s   = gn / EMBED;
        int rem = gn - s * EMBED;
        int h   = rem >> 6;
        int d   = rem & 63;
        float val = Cs[r][c];
        size_t idx = ((size_t)(b * HEADS + h) * SEQ + tok) * HDIM + d;
        if (s == 0)      g_Q[idx] = val * ATT_SCALE;
        else if (s == 1) g_K[idx] = val;
        else             g_V[idx] = val;
    }
}

// ===========================================================================
// Kernel 2: flash attention.  One block per (b,h, 64-row q tile).
// S = Q@K^T via wmma tf32, online softmax in smem, O += P@V via wmma tf32.
// Writes directly to the device-global g_O (NOT passed from host — a
// __device__ symbol used in host code is the host shadow, which was the R1 bug).
// ===========================================================================
#define KV_TILES ((SEQ + 63) / 64)                 // 10
#define ATTN_SMEM ((5 * 64 * 72 + 128) * sizeof(float))   // 92672 B

__global__ void __launch_bounds__(256) attn_kernel()
{
    extern __shared__ float sm[];
    float* Qs   = sm;                  // 64x72 (tf32)
    float* Ks   = Qs + 64 * 72;        // 64x72 (tf32)
    float* Vs   = Ks + 64 * 72;        // 64x72 (tf32)
    float* Ss   = Vs + 64 * 72;        // 64x72 scores (f32) then P (tf32)
    float* Os   = Ss + 64 * 72;        // 64x72 accumulator (f32)
    float* mrow = Os + 64 * 72;        // 64
    float* lrow = mrow + 64;           // 64

    const int tid  = threadIdx.x;
    const int warp = tid >> 5;
    const int wm   = warp >> 1;
    const int wn   = warp & 1;
    const int bh   = blockIdx.y;                 // 0..383
    const int b    = bh / HEADS;
    const int h    = bh - b * HEADS;
    const int q0   = blockIdx.x * 64;

    const float* Qg = g_Q + (size_t)bh * SEQ * HDIM;
    const float* Kg = g_K + (size_t)bh * SEQ * HDIM;
    const float* Vg = g_V + (size_t)bh * SEQ * HDIM;

    // init: Q tile (zero-padded beyond SEQ), O=0, m=-inf, l=0
    for (int i = tid; i < 64 * 16; i += 256) {
        int r  = i >> 4;
        int c4 = (i & 15) << 2;
        int qi = q0 + r;
        float4 v = make_float4(0.f, 0.f, 0.f, 0.f);
        if (qi < SEQ) v = *(const float4*)(Qg + (size_t)qi * HDIM + c4);
        Qs[r * 72 + c4 + 0] = wmma::__float_to_tf32(v.x);
        Qs[r * 72 + c4 + 1] = wmma::__float_to_tf32(v.y);
        Qs[r * 72 + c4 + 2] = wmma::__float_to_tf32(v.z);
        Qs[r * 72 + c4 + 3] = wmma::__float_to_tf32(v.w);
        Os[r * 72 + c4 + 0] = 0.f;
        Os[r * 72 + c4 + 1] = 0.f;
        Os[r * 72 + c4 + 2] = 0.f;
        Os[r * 72 + c4 + 3] = 0.f;
    }
    if (tid < 64) { mrow[tid] = -1e30f; lrow[tid] = 0.f; }

    const int row = tid >> 2;       // softmax role: 4 threads per row
    const int sub = tid & 3;

    for (int kt = 0; kt < KV_TILES; kt++) {
        const int kbase = kt * 64;
        const int valid = min(64, SEQ - kbase);
        __syncthreads();   // prior P@V done with Ks/Vs

        // load K, V tiles (zero-pad invalid keys)
        for (int i = tid; i < 64 * 16; i += 256) {
            int r  = i >> 4;
            int c4 = (i & 15) << 2;
            int ki = kbase + r;
            float4 kv = make_float4(0.f, 0.f, 0.f, 0.f);
            float4 vv = make_float4(0.f, 0.f, 0.f, 0.f);
            if (ki < SEQ) {
                kv = *(const float4*)(Kg + (size_t)ki * HDIM + c4);
                vv = *(const float4*)(Vg + (size_t)ki * HDIM + c4);
            }
            Ks[r * 72 + c4 + 0] = wmma::__float_to_tf32(kv.x);
            Ks[r * 72 + c4 + 1] = wmma::__float_to_tf32(kv.y);
            Ks[r * 72 + c4 + 2] = wmma::__float_to_tf32(kv.z);
            Ks[r * 72 + c4 + 3] = wmma::__float_to_tf32(kv.w);
            Vs[r * 72 + c4 + 0] = wmma::__float_to_tf32(vv.x);
            Vs[r * 72 + c4 + 1] = wmma::__float_to_tf32(vv.y);
            Vs[r * 72 + c4 + 2] = wmma::__float_to_tf32(vv.z);
            Vs[r * 72 + c4 + 3] = wmma::__float_to_tf32(vv.w);
        }
        __syncthreads();

        // S = Q @ K^T  (Q pre-scaled)
        {
            wmma::fragment<wmma::accumulator, 16, 16, 8, float> sacc[2];
            wmma::fill_fragment(sacc[0], 0.0f);
            wmma::fill_fragment(sacc[1], 0.0f);
            #pragma unroll
            for (int kk = 0; kk < 8; kk++) {
                wmma::fragment<wmma::matrix_a, 16, 16, 8, wmma::precision::tf32, wmma::row_major> a;
                wmma::load_matrix_sync(a, &Qs[wm * 16 * 72 + kk * 8], 72);
                #pragma unroll
                for (int j = 0; j < 2; j++) {
                    wmma::fragment<wmma::matrix_b, 16, 16, 8, wmma::precision::tf32, wmma::col_major> bk;
                    wmma::load_matrix_sync(bk, &Ks[(wn * 32 + j * 16) * 72 + kk * 8], 72);
                    wmma::mma_sync(sacc[j], a, bk, sacc[j]);
                }
            }
            wmma::store_matrix_sync(&Ss[wm * 16 * 72 + wn * 32],      sacc[0], 72, wmma::mem_row_major);
            wmma::store_matrix_sync(&Ss[wm * 16 * 72 + wn * 32 + 16], sacc[1], 72, wmma::mem_row_major);
        }
        __syncthreads();

        // online softmax: 4 threads per row (same warp, lanes 4r..4r+3)
        {
            float sv[16];
            float mloc = -1e30f;
            #pragma unroll
            for (int i = 0; i < 16; i++) {
                int c = sub + i * 4;
                float s = (c < valid) ? Ss[row * 72 + c] : -1e30f;
                sv[i] = s;
                mloc = fmaxf(mloc, s);
            }
            mloc = fmaxf(mloc, __shfl_xor_sync(0xffffffffu, mloc, 1));
            mloc = fmaxf(mloc, __shfl_xor_sync(0xffffffffu, mloc, 2));
            float mold = mrow[row];
            float mnew = fmaxf(mold, mloc);
            float alpha = __expf(mold - mnew);
            float lsum = 0.f;
            #pragma unroll
            for (int i = 0; i < 16; i++) {
                int c = sub + i * 4;
                float p = (c < valid) ? __expf(sv[i] - mnew) : 0.f;
                lsum += p;
                Ss[row * 72 + c] = wmma::__float_to_tf32(p);
            }
            lsum += __shfl_xor_sync(0xffffffffu, lsum, 1);
            lsum += __shfl_xor_sync(0xffffffffu, lsum, 2);
            if (sub == 0) {
                mrow[row] = mnew;
                lrow[row] = lrow[row] * alpha + lsum;
            }
            #pragma unroll
            for (int i = 0; i < 16; i++) {
                int c = sub + i * 4;
                Os[row * 72 + c] *= alpha;
            }
        }
        __syncthreads();

        // O += P @ V
        {
            wmma::fragment<wmma::accumulator, 16, 16, 8, float> oc[2];
            wmma::load_matrix_sync(oc[0], &Os[wm * 16 * 72 + wn * 32],      72, wmma::mem_row_major);
            wmma::load_matrix_sync(oc[1], &Os[wm * 16 * 72 + wn * 32 + 16], 72, wmma::mem_row_major);
            #pragma unroll
            for (int kk = 0; kk < 8; kk++) {
                wmma::fragment<wmma::matrix_a, 16, 16, 8, wmma::precision::tf32, wmma::row_major> a;
                wmma::load_matrix_sync(a, &Ss[wm * 16 * 72 + kk * 8], 72);
                #pragma unroll
                for (int j = 0; j < 2; j++) {
                    wmma::fragment<wmma::matrix_b, 16, 16, 8, wmma::precision::tf32, wmma::row_major> bv;
                    wmma::load_matrix_sync(bv, &Vs[kk * 8 * 72 + wn * 32 + j * 16], 72);
                    wmma::mma_sync(oc[j], a, bv, oc[j]);
                }
            }
            wmma::store_matrix_sync(&Os[wm * 16 * 72 + wn * 32],      oc[0], 72, wmma::mem_row_major);
            wmma::store_matrix_sync(&Os[wm * 16 * 72 + wn * 32 + 16], oc[1], 72, wmma::mem_row_major);
        }
    }
    __syncthreads();

    // write normalized O to [b, tok, h*64 + d]
    for (int i = tid; i < 4096; i += 256) {
        int r  = i >> 6;
        int d  = i & 63;
        int qi = q0 + r;
        if (qi >= SEQ) continue;
        float val = Os[r * 72 + d] / lrow[r];
        g_O[((size_t)(b * SEQ + qi)) * EMBED + h * HDIM + d] = val;
    }
}

// ===========================================================================
// Kernel 3: projection GEMM.  out[M,768] = g_O[M,768] @ Wp[768,768] + bias
// ===========================================================================
__global__ void __launch_bounds__(256) gemm_proj_kernel(const float* __restrict__ W,
                                                        const float* __restrict__ bias,
                                                        float* __restrict__ out)
{
    __shared__ float As[64][40];
    __shared__ float Bs[32][72];
    __shared__ float Cs[64][72];

    const int tid  = threadIdx.x;
    const int warp = tid >> 5;
    const int wm   = warp >> 1;
    const int wn   = warp & 1;
    const int m0   = blockIdx.y * 64;
    const int n0   = blockIdx.x * 64;

    wmma::fragment<wmma::accumulator, 16, 16, 8, float> acc[2];
    wmma::fill_fragment(acc[0], 0.0f);
    wmma::fill_fragment(acc[1], 0.0f);

    for (int k0 = 0; k0 < EMBED; k0 += 32) {
        for (int i = tid; i < 512; i += 256) {
            int r  = i >> 3;
            int c4 = (i & 7) << 2;
            int gm = m0 + r;
            float4 v = make_float4(0.f, 0.f, 0.f, 0.f);
            if (gm < MROWS)
                v = *(const float4*)(g_O + (size_t)gm * EMBED + k0 + c4);
            As[r][c4 + 0] = wmma::__float_to_tf32(v.x);
            As[r][c4 + 1] = wmma::__float_to_tf32(v.y);
            As[r][c4 + 2] = wmma::__float_to_tf32(v.z);
            As[r][c4 + 3] = wmma::__float_to_tf32(v.w);
        }
        for (int i = tid; i < 512; i += 256) {
            int r  = i >> 4;
            int c4 = (i & 15) << 2;
            float4 v = *(const float4*)(W + (size_t)(k0 + r) * EMBED + n0 + c4);
            Bs[r][c4 + 0] = wmma::__float_to_tf32(v.x);
            Bs[r][c4 + 1] = wmma::__float_to_tf32(v.y);
            Bs[r][c4 + 2] = wmma::__float_to_tf32(v.z);
            Bs[r][c4 + 3] = wmma::__float_to_tf32(v.w);
        }
        __syncthreads();

        #pragma unroll
        for (int kk = 0; kk < 4; kk++) {
            wmma::fragment<wmma::matrix_a, 16, 16, 8, wmma::precision::tf32, wmma::row_major> a;
            wmma::load_matrix_sync(a, &As[wm * 16][kk * 8], 40);
            #pragma unroll
            for (int j = 0; j < 2; j++) {
                wmma::fragment<wmma::matrix_b, 16, 16, 8, wmma::precision::tf32, wmma::row_major> b;
                wmma::load_matrix_sync(b, &Bs[kk * 8][wn * 32 + j * 16], 72);
                wmma::mma_sync(acc[j], a, b, acc[j]);
            }
        }
        __syncthreads();
    }

    wmma::store_matrix_sync(&Cs[wm * 16][wn * 32],      acc[0], 72, wmma::mem_row_major);
    wmma::store_matrix_sync(&Cs[wm * 16][wn * 32 + 16], acc[1], 72, wmma::mem_row_major);
    __syncthreads();

    for (int i = tid; i < 4096; i += 256) {
        int r  = i >> 6;
        int c  = i & 63;
        int gm = m0 + r;
        if (gm >= MROWS) continue;
        int gn = n0 + c;
        out[(size_t)gm * EMBED + gn] = Cs[r][c] + bias[gn];
    }
}

// ===========================================================================
extern "C" void kernel_launch(void* const* d_in, const int* in_sizes, int n_in,
                              void* d_out, int out_size)
{
    (void)in_sizes; (void)n_in; (void)out_size;
    const float* x      = (const float*)d_in[0];
    const float* w_qkv  = (const float*)d_in[1];
    const float* w_proj = (const float*)d_in[2];
    const float* b_proj = (const float*)d_in[3];
    float* out = (float*)d_out;

    cudaFuncSetAttribute(attn_kernel, cudaFuncAttributeMaxDynamicSharedMemorySize,
                         (int)ATTN_SMEM);

    // QKV: grid (N/64 = 36, ceil(M/64) = 289)
    gemm_qkv_kernel<<<dim3(36, 289), 256>>>(x, w_qkv);
    // attention: (q-tiles = 10, B*H = 384)
    attn_kernel<<<dim3(10, 384), 256, ATTN_SMEM>>>();
    // projection: (768/64 = 12, 289)
    gemm_proj_kernel<<<dim3(12, 289), 256>>>(w_proj, b_proj, out);
}

// round 3
// speedup vs baseline: 1.1288x; 1.1288x over previous
#include <cuda_runtime.h>
#include <mma.h>
#include <cstdint>

using namespace nvcuda;

#define BATCH   32
#define SEQ     577
#define EMBED   768
#define HEADS   12
#define HDIM    64
#define MROWS   (BATCH * SEQ)        // 18464
#define QKV_N   (3 * EMBED)          // 2304
#define ATT_SCALE 0.125f             // HDIM^-0.5

// ---------------- scratch (module-load allocated, no runtime allocs) -------
__device__ float g_Q[(size_t)BATCH * HEADS * SEQ * HDIM];   // [b,h,n,d], pre-scaled
__device__ float g_K[(size_t)BATCH * HEADS * SEQ * HDIM];
__device__ float g_V[(size_t)BATCH * HEADS * SEQ * HDIM];
__device__ float g_O[(size_t)MROWS * EMBED];                // attention out [b,n, h*64+d]

// ---------------- cp.async helpers ----------------------------------------
__device__ __forceinline__ uint32_t smem_u32(const void* p) {
    uint32_t a;
    asm("{ .reg .u64 t; cvta.to.shared.u64 t, %1; cvt.u32.u64 %0, t; }"
        : "=r"(a) : "l"(p));
    return a;
}
__device__ __forceinline__ void cp16(uint32_t dst, const void* src, bool pred) {
    int sz = pred ? 16 : 0;
    asm volatile("cp.async.cg.shared.global [%0], [%1], 16, %2;\n"
                 :: "r"(dst), "l"(src), "r"(sz));
}
#define CP_COMMIT() asm volatile("cp.async.commit_group;\n" ::: "memory")
#define CP_WAIT1()  asm volatile("cp.async.wait_group 1;\n" ::: "memory")
#define CP_WAIT0()  asm volatile("cp.async.wait_group 0;\n" ::: "memory")

// ---------------- GEMM tiling constants -----------------------------------
// BM=128, BN=64, BK=32; 256 threads = 8 warps as 4(m) x 2(n); warp tile 32x32.
#define BM 128
#define BN 64
#define BK 32
#define LDA 36                       // A row stride in smem (floats), 144B (16B-aligned)
#define LDB 68                       // B row stride in smem (floats), 272B (16B-aligned)
#define LDC 68
#define A_STAGE (BM * LDA)           // 4608 floats
#define B_STAGE (BK * LDB)           // 2176 floats
#define GEMM_SMEM_FLOATS (2 * (A_STAGE + B_STAGE))   // 13568
#define GEMM_SMEM_BYTES  (GEMM_SMEM_FLOATS * 4)      // 54272 (epilogue reuses: 128*68=8704 floats)
#define KTILES (EMBED / BK)          // 24

template <typename FA>
__device__ __forceinline__ void cvt_frag_tf32(FA& f) {
    #pragma unroll
    for (int i = 0; i < f.num_elements; i++) f.x[i] = wmma::__float_to_tf32(f.x[i]);
}

// Shared mainloop: accumulates C(128x64) tile of  A_g[M,K=768] @ B_g[768,ldb-N-matrix].
// acc indexed [mi][ni] (2x2 of 16x16). Caller does epilogue via smem Cs = sm.
__device__ __forceinline__ void gemm_mainloop(
    const float* __restrict__ Ag, int lda_g, int m0, bool mtail,
    const float* __restrict__ Bg, int ldb_g, int n0,
    float* sm,
    wmma::fragment<wmma::accumulator, 16, 16, 8, float> (&acc)[2][2])
{
    float* sA = sm;
    float* sB = sm + 2 * A_STAGE;

    const int tid  = threadIdx.x;
    const int warp = tid >> 5;
    const int wm   = warp >> 1;     // 0..3
    const int wn   = warp & 1;      // 0..1

    // per-thread load indices
    // A: 1024 float4 -> 4/thread.  r = i>>3 (0..127), c4 = (i&7)*4
    // B: 512  float4 -> 2/thread.  r = i>>4 (0..31),  c4 = (i&15)*4
    uint32_t sA_u = smem_u32(sA);
    uint32_t sB_u = smem_u32(sB);

    auto issue = [&](int kt, int st) {
        const int k0 = kt * BK;
        #pragma unroll
        for (int j = 0; j < 4; j++) {
            int i  = tid + j * 256;
            int r  = i >> 3;
            int c4 = (i & 7) << 2;
            int gm = m0 + r;
            bool p = !mtail || (gm < MROWS);
            cp16(sA_u + (uint32_t)(st * A_STAGE + r * LDA + c4) * 4,
                 Ag + (size_t)gm * lda_g + k0 + c4, p);
        }
        #pragma unroll
        for (int j = 0; j < 2; j++) {
            int i  = tid + j * 256;
            int r  = i >> 4;
            int c4 = (i & 15) << 2;
            cp16(sB_u + (uint32_t)(st * B_STAGE + r * LDB + c4) * 4,
                 Bg + (size_t)(k0 + r) * ldb_g + n0 + c4, true);
        }
        CP_COMMIT();
    };

    issue(0, 0);

    for (int it = 0; it < KTILES; it++) {
        const int st = it & 1;
        if (it + 1 < KTILES) issue(it + 1, st ^ 1);
        if (it + 1 < KTILES) CP_WAIT1(); else CP_WAIT0();
        __syncthreads();

        const float* At = sA + st * A_STAGE + wm * 32 * LDA;
        const float* Bt = sB + st * B_STAGE + wn * 32;
        #pragma unroll
        for (int kk = 0; kk < BK / 8; kk++) {
            wmma::fragment<wmma::matrix_a, 16, 16, 8, wmma::precision::tf32, wmma::row_major> a0, a1;
            wmma::load_matrix_sync(a0, At + kk * 8, LDA);
            wmma::load_matrix_sync(a1, At + 16 * LDA + kk * 8, LDA);
            cvt_frag_tf32(a0); cvt_frag_tf32(a1);
            wmma::fragment<wmma::matrix_b, 16, 16, 8, wmma::precision::tf32, wmma::row_major> b0, b1;
            wmma::load_matrix_sync(b0, Bt + kk * 8 * LDB, LDB);
            wmma::load_matrix_sync(b1, Bt + kk * 8 * LDB + 16, LDB);
            cvt_frag_tf32(b0); cvt_frag_tf32(b1);
            wmma::mma_sync(acc[0][0], a0, b0, acc[0][0]);
            wmma::mma_sync(acc[0][1], a0, b1, acc[0][1]);
            wmma::mma_sync(acc[1][0], a1, b0, acc[1][0]);
            wmma::mma_sync(acc[1][1], a1, b1, acc[1][1]);
        }
        __syncthreads();
    }
}

// ===========================================================================
// Kernel 1: QKV GEMM + scatter epilogue into g_Q/g_K/g_V ([B,H,N,Dh], Q scaled)
// ===========================================================================
__global__ void __launch_bounds__(256) gemm_qkv_kernel(const float* __restrict__ X,
                                                       const float* __restrict__ W)
{
    extern __shared__ float sm[];
    const int tid  = threadIdx.x;
    const int warp = tid >> 5;
    const int wm   = warp >> 1;
    const int wn   = warp & 1;
    const int m0   = blockIdx.y * BM;
    const int n0   = blockIdx.x * BN;
    const bool mtail = (m0 + BM > MROWS);

    wmma::fragment<wmma::accumulator, 16, 16, 8, float> acc[2][2];
    #pragma unroll
    for (int i = 0; i < 2; i++)
        #pragma unroll
        for (int j = 0; j < 2; j++) wmma::fill_fragment(acc[i][j], 0.0f);

    gemm_mainloop(X, EMBED, m0, mtail, W, QKV_N, n0, sm, acc);

    // epilogue: reuse smem as Cs[128][68]
    float* Cs = sm;
    #pragma unroll
    for (int i = 0; i < 2; i++)
        #pragma unroll
        for (int j = 0; j < 2; j++)
            wmma::store_matrix_sync(&Cs[(wm * 32 + i * 16) * LDC + wn * 32 + j * 16],
                                    acc[i][j], LDC, wmma::mem_row_major);
    __syncthreads();

    for (int i = tid; i < BM * BN; i += 256) {
        int r  = i >> 6;
        int c  = i & 63;
        int gm = m0 + r;
        if (gm >= MROWS) continue;
        int gn  = n0 + c;
        int b   = gm / SEQ;
        int tok = gm - b * SEQ;
        int s   = gn / EMBED;
        int rem = gn - s * EMBED;
        int h   = rem >> 6;
        int d   = rem & 63;
        float val = Cs[r * LDC + c];
        size_t idx = ((size_t)(b * HEADS + h) * SEQ + tok) * HDIM + d;
        if (s == 0)      g_Q[idx] = val * ATT_SCALE;
        else if (s == 1) g_K[idx] = val;
        else             g_V[idx] = val;
    }
}

// ===========================================================================
// Kernel 3: projection GEMM.  out[M,768] = g_O[M,768] @ Wp[768,768] + bias
// ===========================================================================
__global__ void __launch_bounds__(256) gemm_proj_kernel(const float* __restrict__ W,
                                                        const float* __restrict__ bias,
                                                        float* __restrict__ out)
{
    extern __shared__ float sm[];
    const int tid  = threadIdx.x;
    const int warp = tid >> 5;
    const int wm   = warp >> 1;
    const int wn   = warp & 1;
    const int m0   = blockIdx.y * BM;
    const int n0   = blockIdx.x * BN;
    const bool mtail = (m0 + BM > MROWS);

    wmma::fragment<wmma::accumulator, 16, 16, 8, float> acc[2][2];
    #pragma unroll
    for (int i = 0; i < 2; i++)
        #pragma unroll
        for (int j = 0; j < 2; j++) wmma::fill_fragment(acc[i][j], 0.0f);

    gemm_mainloop(g_O, EMBED, m0, mtail, W, EMBED, n0, sm, acc);

    float* Cs = sm;
    #pragma unroll
    for (int i = 0; i < 2; i++)
        #pragma unroll
        for (int j = 0; j < 2; j++)
            wmma::store_matrix_sync(&Cs[(wm * 32 + i * 16) * LDC + wn * 32 + j * 16],
                                    acc[i][j], LDC, wmma::mem_row_major);
    __syncthreads();

    for (int i = tid; i < BM * BN; i += 256) {
        int r  = i >> 6;
        int c  = i & 63;
        int gm = m0 + r;
        if (gm >= MROWS) continue;
        int gn = n0 + c;
        out[(size_t)gm * EMBED + gn] = Cs[r * LDC + c] + bias[gn];
    }
}

// ===========================================================================
// Kernel 2: flash attention (unchanged from R2). One block per (b,h, 64-q tile).
// ===========================================================================
#define KV_TILES ((SEQ + 63) / 64)                 // 10
#define ATTN_SMEM ((5 * 64 * 72 + 128) * sizeof(float))   // 92672 B

__global__ void __launch_bounds__(256) attn_kernel()
{
    extern __shared__ float smf[];
    float* Qs   = smf;                 // 64x72 (tf32)
    float* Ks   = Qs + 64 * 72;
    float* Vs   = Ks + 64 * 72;
    float* Ss   = Vs + 64 * 72;
    float* Os   = Ss + 64 * 72;
    float* mrow = Os + 64 * 72;        // 64
    float* lrow = mrow + 64;           // 64

    const int tid  = threadIdx.x;
    const int warp = tid >> 5;
    const int wm   = warp >> 1;
    const int wn   = warp & 1;
    const int bh   = blockIdx.y;
    const int b    = bh / HEADS;
    const int h    = bh - b * HEADS;
    const int q0   = blockIdx.x * 64;

    const float* Qg = g_Q + (size_t)bh * SEQ * HDIM;
    const float* Kg = g_K + (size_t)bh * SEQ * HDIM;
    const float* Vg = g_V + (size_t)bh * SEQ * HDIM;

    for (int i = tid; i < 64 * 16; i += 256) {
        int r  = i >> 4;
        int c4 = (i & 15) << 2;
        int qi = q0 + r;
        float4 v = make_float4(0.f, 0.f, 0.f, 0.f);
        if (qi < SEQ) v = *(const float4*)(Qg + (size_t)qi * HDIM + c4);
        Qs[r * 72 + c4 + 0] = wmma::__float_to_tf32(v.x);
        Qs[r * 72 + c4 + 1] = wmma::__float_to_tf32(v.y);
        Qs[r * 72 + c4 + 2] = wmma::__float_to_tf32(v.z);
        Qs[r * 72 + c4 + 3] = wmma::__float_to_tf32(v.w);
        Os[r * 72 + c4 + 0] = 0.f;
        Os[r * 72 + c4 + 1] = 0.f;
        Os[r * 72 + c4 + 2] = 0.f;
        Os[r * 72 + c4 + 3] = 0.f;
    }
    if (tid < 64) { mrow[tid] = -1e30f; lrow[tid] = 0.f; }

    const int row = tid >> 2;
    const int sub = tid & 3;

    for (int kt = 0; kt < KV_TILES; kt++) {
        const int kbase = kt * 64;
        const int valid = min(64, SEQ - kbase);
        __syncthreads();

        for (int i = tid; i < 64 * 16; i += 256) {
            int r  = i >> 4;
            int c4 = (i & 15) << 2;
            int ki = kbase + r;
            float4 kv = make_float4(0.f, 0.f, 0.f, 0.f);
            float4 vv = make_float4(0.f, 0.f, 0.f, 0.f);
            if (ki < SEQ) {
                kv = *(const float4*)(Kg + (size_t)ki * HDIM + c4);
                vv = *(const float4*)(Vg + (size_t)ki * HDIM + c4);
            }
            Ks[r * 72 + c4 + 0] = wmma::__float_to_tf32(kv.x);
            Ks[r * 72 + c4 + 1] = wmma::__float_to_tf32(kv.y);
            Ks[r * 72 + c4 + 2] = wmma::__float_to_tf32(kv.z);
            Ks[r * 72 + c4 + 3] = wmma::__float_to_tf32(kv.w);
            Vs[r * 72 + c4 + 0] = wmma::__float_to_tf32(vv.x);
            Vs[r * 72 + c4 + 1] = wmma::__float_to_tf32(vv.y);
            Vs[r * 72 + c4 + 2] = wmma::__float_to_tf32(vv.z);
            Vs[r * 72 + c4 + 3] = wmma::__float_to_tf32(vv.w);
        }
        __syncthreads();

        {
            wmma::fragment<wmma::accumulator, 16, 16, 8, float> sacc[2];
            wmma::fill_fragment(sacc[0], 0.0f);
            wmma::fill_fragment(sacc[1], 0.0f);
            #pragma unroll
            for (int kk = 0; kk < 8; kk++) {
                wmma::fragment<wmma::matrix_a, 16, 16, 8, wmma::precision::tf32, wmma::row_major> a;
                wmma::load_matrix_sync(a, &Qs[wm * 16 * 72 + kk * 8], 72);
                #pragma unroll
                for (int j = 0; j < 2; j++) {
                    wmma::fragment<wmma::matrix_b, 16, 16, 8, wmma::precision::tf32, wmma::col_major> bk;
                    wmma::load_matrix_sync(bk, &Ks[(wn * 32 + j * 16) * 72 + kk * 8], 72);
                    wmma::mma_sync(sacc[j], a, bk, sacc[j]);
                }
            }
            wmma::store_matrix_sync(&Ss[wm * 16 * 72 + wn * 32],      sacc[0], 72, wmma::mem_row_major);
            wmma::store_matrix_sync(&Ss[wm * 16 * 72 + wn * 32 + 16], sacc[1], 72, wmma::mem_row_major);
        }
        __syncthreads();

        {
            float sv[16];
            float mloc = -1e30f;
            #pragma unroll
            for (int i = 0; i < 16; i++) {
                int c = sub + i * 4;
                float s = (c < valid) ? Ss[row * 72 + c] : -1e30f;
                sv[i] = s;
                mloc = fmaxf(mloc, s);
            }
            mloc = fmaxf(mloc, __shfl_xor_sync(0xffffffffu, mloc, 1));
            mloc = fmaxf(mloc, __shfl_xor_sync(0xffffffffu, mloc, 2));
            float mold = mrow[row];
            float mnew = fmaxf(mold, mloc);
            float alpha = __expf(mold - mnew);
            float lsum = 0.f;
            #pragma unroll
            for (int i = 0; i < 16; i++) {
                int c = sub + i * 4;
                float p = (c < valid) ? __expf(sv[i] - mnew) : 0.f;
                lsum += p;
                Ss[row * 72 + c] = wmma::__float_to_tf32(p);
            }
            lsum += __shfl_xor_sync(0xffffffffu, lsum, 1);
            lsum += __shfl_xor_sync(0xffffffffu, lsum, 2);
            if (sub == 0) {
                mrow[row] = mnew;
                lrow[row] = lrow[row] * alpha + lsum;
            }
            #pragma unroll
            for (int i = 0; i < 16; i++) {
                int c = sub + i * 4;
                Os[row * 72 + c] *= alpha;
            }
        }
        __syncthreads();

        {
            wmma::fragment<wmma::accumulator, 16, 16, 8, float> oc[2];
            wmma::load_matrix_sync(oc[0], &Os[wm * 16 * 72 + wn * 32],      72, wmma::mem_row_major);
            wmma::load_matrix_sync(oc[1], &Os[wm * 16 * 72 + wn * 32 + 16], 72, wmma::mem_row_major);
            #pragma unroll
            for (int kk = 0; kk < 8; kk++) {
                wmma::fragment<wmma::matrix_a, 16, 16, 8, wmma::precision::tf32, wmma::row_major> a;
                wmma::load_matrix_sync(a, &Ss[wm * 16 * 72 + kk * 8], 72);
                #pragma unroll
                for (int j = 0; j < 2; j++) {
                    wmma::fragment<wmma::matrix_b, 16, 16, 8, wmma::precision::tf32, wmma::row_major> bv;
                    wmma::load_matrix_sync(bv, &Vs[kk * 8 * 72 + wn * 32 + j * 16], 72);
                    wmma::mma_sync(oc[j], a, bv, oc[j]);
                }
            }
            wmma::store_matrix_sync(&Os[wm * 16 * 72 + wn * 32],      oc[0], 72, wmma::mem_row_major);
            wmma::store_matrix_sync(&Os[wm * 16 * 72 + wn * 32 + 16], oc[1], 72, wmma::mem_row_major);
        }
    }
    __syncthreads();

    for (int i = tid; i < 4096; i += 256) {
        int r  = i >> 6;
        int d  = i & 63;
        int qi = q0 + r;
        if (qi >= SEQ) continue;
        float val = Os[r * 72 + d] / lrow[r];
        g_O[((size_t)(b * SEQ + qi)) * EMBED + h * HDIM + d] = val;
    }
}

// ===========================================================================
extern "C" void kernel_launch(void* const* d_in, const int* in_sizes, int n_in,
                              void* d_out, int out_size)
{
    (void)in_sizes; (void)n_in; (void)out_size;
    const float* x      = (const float*)d_in[0];
    const float* w_qkv  = (const float*)d_in[1];
    const float* w_proj = (const float*)d_in[2];
    const float* b_proj = (const float*)d_in[3];
    float* out = (float*)d_out;

    cudaFuncSetAttribute(gemm_qkv_kernel,  cudaFuncAttributeMaxDynamicSharedMemorySize, GEMM_SMEM_BYTES);
    cudaFuncSetAttribute(gemm_proj_kernel, cudaFuncAttributeMaxDynamicSharedMemorySize, GEMM_SMEM_BYTES);
    cudaFuncSetAttribute(attn_kernel,      cudaFuncAttributeMaxDynamicSharedMemorySize, (int)ATTN_SMEM);

    const int mblocks = (MROWS + BM - 1) / BM;   // 145

    gemm_qkv_kernel<<<dim3(QKV_N / BN, mblocks), 256, GEMM_SMEM_BYTES>>>(x, w_qkv);
    attn_kernel<<<dim3(KV_TILES, BATCH * HEADS), 256, ATTN_SMEM>>>();
    gemm_proj_kernel<<<dim3(EMBED / BN, mblocks), 256, GEMM_SMEM_BYTES>>>(w_proj, b_proj, out);
}

// round 5
// speedup vs baseline: 3.3574x; 2.9742x over previous
#include <cuda_runtime.h>
#include <cuda_fp16.h>
#include <mma.h>
#include <cstdint>

using namespace nvcuda;

#define BATCH   32
#define SEQ     577
#define EMBED   768
#define HEADS   12
#define HDIM    64
#define MROWS   (BATCH * SEQ)        // 18464
#define QKV_N   (3 * EMBED)          // 2304
#define ATT_SCALE 0.125f             // HDIM^-0.5

// ---------------- scratch (module-load allocated, no runtime allocs) -------
__device__ __half g_Qh[(size_t)BATCH * HEADS * SEQ * HDIM];   // [b,h,n,d], pre-scaled
__device__ __half g_Kh[(size_t)BATCH * HEADS * SEQ * HDIM];
__device__ __half g_Vh[(size_t)BATCH * HEADS * SEQ * HDIM];
__device__ __half g_Oh[(size_t)MROWS * EMBED];                // attention out (half)
__device__ __half g_Xh[(size_t)MROWS * EMBED];                // half X
__device__ __half g_Wqkvh[(size_t)EMBED * QKV_N];             // half W_qkv (row-major)
__device__ __half g_Wprojh[(size_t)EMBED * EMBED];            // half W_proj (row-major)

// ---------------- cp.async helpers ----------------------------------------
__device__ __forceinline__ uint32_t smem_u32(const void* p) {
    uint32_t a;
    asm("{ .reg .u64 t; cvta.to.shared.u64 t, %1; cvt.u32.u64 %0, t; }"
        : "=r"(a) : "l"(p));
    return a;
}
__device__ __forceinline__ void cp16(uint32_t dst, const void* src, bool pred) {
    int sz = pred ? 16 : 0;
    asm volatile("cp.async.cg.shared.global [%0], [%1], 16, %2;\n"
                 :: "r"(dst), "l"(src), "r"(sz));
}
#define CP_COMMIT() asm volatile("cp.async.commit_group;\n" ::: "memory")
#define CP_WAIT1()  asm volatile("cp.async.wait_group 1;\n" ::: "memory")
#define CP_WAIT0()  asm volatile("cp.async.wait_group 0;\n" ::: "memory")

// ---------------- GEMM tiling (fp16 mma.sync m16n16k16) --------------------
// BM=128, BN=64, BK=32; 256 threads = 8 warps as 4(m) x 2(n); warp tile 32x32.
#define BM 128
#define BN 64
#define BK 32
#define LDA 40                       // A smem row stride (halves), 80B (16B-aligned)
#define LDB 72                       // B smem row stride (halves), 144B
#define LDC 68                       // epilogue floats
#define A_STAGE (BM * LDA)           // 5120 halves
#define B_STAGE (BK * LDB)           // 2304 halves
#define GEMM_SMEM_BYTES 35328        // max(mainloop 29696B, Cs 128*68*4=34816B) + pad
#define KTILES (EMBED / BK)          // 24

// Shared mainloop: acc[2][2] += A[m0:+128, 0:768] @ B[0:768, n0:+64]
__device__ __forceinline__ void gemm_mainloop_h(
    const __half* __restrict__ Ag, int lda_g, int m0, bool mtail,
    const __half* __restrict__ Bg, int ldb_g, int n0,
    __half* sm,
    wmma::fragment<wmma::accumulator, 16, 16, 16, float> (&acc)[2][2])
{
    __half* sA = sm;
    __half* sB = sm + 2 * A_STAGE;

    const int tid  = threadIdx.x;
    const int warp = tid >> 5;
    const int wm   = warp >> 1;
    const int wn   = warp & 1;

    uint32_t sA_u = smem_u32(sA);
    uint32_t sB_u = smem_u32(sB);

    auto issue = [&](int kt, int st) {
        const int k0 = kt * BK;
        // A: 128 rows x 32 halves = 512 chunks of 8 halves -> 2/thread
        #pragma unroll
        for (int j = 0; j < 2; j++) {
            int i  = tid + j * 256;
            int r  = i >> 2;
            int ch = i & 3;
            int gm = m0 + r;
            bool p = !mtail || (gm < MROWS);
            cp16(sA_u + (uint32_t)(st * A_STAGE + r * LDA + ch * 8) * 2,
                 Ag + (size_t)gm * lda_g + k0 + ch * 8, p);
        }
        // B: 32 rows x 64 halves = 256 chunks of 8 -> 1/thread
        {
            int r  = tid >> 3;
            int ch = tid & 7;
            cp16(sB_u + (uint32_t)(st * B_STAGE + r * LDB + ch * 8) * 2,
                 Bg + (size_t)(k0 + r) * ldb_g + n0 + ch * 8, true);
        }
        CP_COMMIT();
    };

    issue(0, 0);

    for (int it = 0; it < KTILES; it++) {
        const int st = it & 1;
        if (it + 1 < KTILES) { issue(it + 1, st ^ 1); CP_WAIT1(); }
        else                 { CP_WAIT0(); }
        __syncthreads();

        const __half* At = sA + st * A_STAGE + wm * 32 * LDA;
        const __half* Bt = sB + st * B_STAGE + wn * 32;
        #pragma unroll
        for (int kk = 0; kk < BK / 16; kk++) {
            wmma::fragment<wmma::matrix_a, 16, 16, 16, __half, wmma::row_major> a0, a1;
            wmma::load_matrix_sync(a0, At + kk * 16, LDA);
            wmma::load_matrix_sync(a1, At + 16 * LDA + kk * 16, LDA);
            wmma::fragment<wmma::matrix_b, 16, 16, 16, __half, wmma::row_major> b0, b1;
            wmma::load_matrix_sync(b0, Bt + kk * 16 * LDB, LDB);
            wmma::load_matrix_sync(b1, Bt + kk * 16 * LDB + 16, LDB);
            wmma::mma_sync(acc[0][0], a0, b0, acc[0][0]);
            wmma::mma_sync(acc[0][1], a0, b1, acc[0][1]);
            wmma::mma_sync(acc[1][0], a1, b0, acc[1][0]);
            wmma::mma_sync(acc[1][1], a1, b1, acc[1][1]);
        }
        __syncthreads();
    }
}

// ===========================================================================
// Kernel 1: QKV GEMM + scatter epilogue into g_Qh/g_Kh/g_Vh (half, Q scaled)
// ===========================================================================
__global__ void __launch_bounds__(256) gemm_qkv_kernel(const __half* __restrict__ X,
                                                       const __half* __restrict__ W)
{
    extern __shared__ __half smh[];
    const int tid  = threadIdx.x;
    const int warp = tid >> 5;
    const int wm   = warp >> 1;
    const int wn   = warp & 1;
    const int m0   = blockIdx.y * BM;
    const int n0   = blockIdx.x * BN;
    const bool mtail = (m0 + BM > MROWS);

    wmma::fragment<wmma::accumulator, 16, 16, 16, float> acc[2][2];
    #pragma unroll
    for (int i = 0; i < 2; i++)
        #pragma unroll
        for (int j = 0; j < 2; j++) wmma::fill_fragment(acc[i][j], 0.0f);

    gemm_mainloop_h(X, EMBED, m0, mtail, W, QKV_N, n0, smh, acc);

    float* Cs = (float*)smh;
    #pragma unroll
    for (int i = 0; i < 2; i++)
        #pragma unroll
        for (int j = 0; j < 2; j++)
            wmma::store_matrix_sync(&Cs[(wm * 32 + i * 16) * LDC + wn * 32 + j * 16],
                                    acc[i][j], LDC, wmma::mem_row_major);
    __syncthreads();

    for (int i = tid; i < BM * BN; i += 256) {
        int r  = i >> 6;
        int c  = i & 63;
        int gm = m0 + r;
        if (gm >= MROWS) continue;
        int gn  = n0 + c;
        int b   = gm / SEQ;
        int tok = gm - b * SEQ;
        int s   = gn / EMBED;
        int rem = gn - s * EMBED;
        int h   = rem >> 6;
        int d   = rem & 63;
        float val = Cs[r * LDC + c];
        size_t idx = ((size_t)(b * HEADS + h) * SEQ + tok) * HDIM + d;
        if (s == 0)      g_Qh[idx] = __float2half_rn(val * ATT_SCALE);
        else if (s == 1) g_Kh[idx] = __float2half_rn(val);
        else             g_Vh[idx] = __float2half_rn(val);
    }
}

// ===========================================================================
// Kernel 3: projection GEMM.  out = g_Oh @ Wp + bias  (fp32 out)
// ===========================================================================
__global__ void __launch_bounds__(256) gemm_proj_kernel(const __half* __restrict__ A,
                                                        const __half* __restrict__ W,
                                                        const float* __restrict__ bias,
                                                        float* __restrict__ out)
{
    extern __shared__ __half smh[];
    const int tid  = threadIdx.x;
    const int warp = tid >> 5;
    const int wm   = warp >> 1;
    const int wn   = warp & 1;
    const int m0   = blockIdx.y * BM;
    const int n0   = blockIdx.x * BN;
    const bool mtail = (m0 + BM > MROWS);

    wmma::fragment<wmma::accumulator, 16, 16, 16, float> acc[2][2];
    #pragma unroll
    for (int i = 0; i < 2; i++)
        #pragma unroll
        for (int j = 0; j < 2; j++) wmma::fill_fragment(acc[i][j], 0.0f);

    gemm_mainloop_h(A, EMBED, m0, mtail, W, EMBED, n0, smh, acc);

    float* Cs = (float*)smh;
    #pragma unroll
    for (int i = 0; i < 2; i++)
        #pragma unroll
        for (int j = 0; j < 2; j++)
            wmma::store_matrix_sync(&Cs[(wm * 32 + i * 16) * LDC + wn * 32 + j * 16],
                                    acc[i][j], LDC, wmma::mem_row_major);
    __syncthreads();

    for (int i = tid; i < BM * BN; i += 256) {
        int r  = i >> 6;
        int c  = i & 63;
        int gm = m0 + r;
        if (gm >= MROWS) continue;
        int gn = n0 + c;
        out[(size_t)gm * EMBED + gn] = Cs[r * LDC + c] + bias[gn];
    }
}

// ===========================================================================
// Kernel 2: flash attention, fp16 MMA. One block per (b,h, 64-q tile).
// smem: Ss(f32 64x72), Os(f32 64x72), mrow/lrow, Qs/Ks/Vs/Ps (half 64x72)
// ===========================================================================
#define KV_TILES ((SEQ + 63) / 64)                 // 10
#define LDH 72
#define ATTN_SMEM (2 * 64 * 72 * 4 + 128 * 4 + 4 * 64 * 72 * 2)   // 74240 B

__global__ void __launch_bounds__(256) attn_kernel()
{
    extern __shared__ char smraw[];
    float*  Ss   = (float*)smraw;                   // 64x72 f32
    float*  Os   = Ss + 64 * LDH;                   // 64x72 f32
    float*  mrow = Os + 64 * LDH;                   // 64
    float*  lrow = mrow + 64;                       // 64
    __half* Qs   = (__half*)(lrow + 64);            // 64x72 h
    __half* Ks   = Qs + 64 * LDH;
    __half* Vs   = Ks + 64 * LDH;
    __half* Ps   = Vs + 64 * LDH;

    const int tid  = threadIdx.x;
    const int warp = tid >> 5;
    const int wm   = warp >> 1;
    const int wn   = warp & 1;
    const int bh   = blockIdx.y;
    const int b    = bh / HEADS;
    const int h    = bh - b * HEADS;
    const int q0   = blockIdx.x * 64;

    const __half* Qg = g_Qh + (size_t)bh * SEQ * HDIM;
    const __half* Kg = g_Kh + (size_t)bh * SEQ * HDIM;
    const __half* Vg = g_Vh + (size_t)bh * SEQ * HDIM;

    // init: Q tile (zero-pad beyond SEQ), O=0, m,l
    for (int i = tid; i < 64 * 8; i += 256) {       // 8 chunks of 8 halves per row
        int r  = i >> 3;
        int c8 = (i & 7) << 3;
        int qi = q0 + r;
        uint4 v = make_uint4(0, 0, 0, 0);
        if (qi < SEQ) v = *(const uint4*)(Qg + (size_t)qi * HDIM + c8);
        *(uint4*)(Qs + r * LDH + c8) = v;
    }
    for (int i = tid; i < 64 * 16; i += 256) {
        int r  = i >> 4;
        int c4 = (i & 15) << 2;
        *(float4*)(Os + r * LDH + c4) = make_float4(0.f, 0.f, 0.f, 0.f);
    }
    if (tid < 64) { mrow[tid] = -1e30f; lrow[tid] = 0.f; }

    const int row = tid >> 2;
    const int sub = tid & 3;

    for (int kt = 0; kt < KV_TILES; kt++) {
        const int kbase = kt * 64;
        const int valid = min(64, SEQ - kbase);
        __syncthreads();   // prior P@V done with Ks/Vs

        for (int i = tid; i < 64 * 8; i += 256) {
            int r  = i >> 3;
            int c8 = (i & 7) << 3;
            int ki = kbase + r;
            uint4 kv = make_uint4(0, 0, 0, 0);
            uint4 vv = make_uint4(0, 0, 0, 0);
            if (ki < SEQ) {
                kv = *(const uint4*)(Kg + (size_t)ki * HDIM + c8);
                vv = *(const uint4*)(Vg + (size_t)ki * HDIM + c8);
            }
            *(uint4*)(Ks + r * LDH + c8) = kv;
            *(uint4*)(Vs + r * LDH + c8) = vv;
        }
        __syncthreads();

        // S = Q @ K^T  (Q pre-scaled)
        {
            wmma::fragment<wmma::accumulator, 16, 16, 16, float> sacc[2];
            wmma::fill_fragment(sacc[0], 0.0f);
            wmma::fill_fragment(sacc[1], 0.0f);
            #pragma unroll
            for (int kk = 0; kk < HDIM / 16; kk++) {
                wmma::fragment<wmma::matrix_a, 16, 16, 16, __half, wmma::row_major> a;
                wmma::load_matrix_sync(a, &Qs[wm * 16 * LDH + kk * 16], LDH);
                #pragma unroll
                for (int j = 0; j < 2; j++) {
                    wmma::fragment<wmma::matrix_b, 16, 16, 16, __half, wmma::col_major> bk;
                    wmma::load_matrix_sync(bk, &Ks[(wn * 32 + j * 16) * LDH + kk * 16], LDH);
                    wmma::mma_sync(sacc[j], a, bk, sacc[j]);
                }
            }
            wmma::store_matrix_sync(&Ss[wm * 16 * LDH + wn * 32],      sacc[0], LDH, wmma::mem_row_major);
            wmma::store_matrix_sync(&Ss[wm * 16 * LDH + wn * 32 + 16], sacc[1], LDH, wmma::mem_row_major);
        }
        __syncthreads();

        // online softmax (4 threads/row), P -> half
        {
            float sv[16];
            float mloc = -1e30f;
            #pragma unroll
            for (int i = 0; i < 16; i++) {
                int c = sub + i * 4;
                float s = (c < valid) ? Ss[row * LDH + c] : -1e30f;
                sv[i] = s;
                mloc = fmaxf(mloc, s);
            }
            mloc = fmaxf(mloc, __shfl_xor_sync(0xffffffffu, mloc, 1));
            mloc = fmaxf(mloc, __shfl_xor_sync(0xffffffffu, mloc, 2));
            float mold = mrow[row];
            float mnew = fmaxf(mold, mloc);
            float alpha = __expf(mold - mnew);
            float lsum = 0.f;
            #pragma unroll
            for (int i = 0; i < 16; i++) {
                int c = sub + i * 4;
                float p = (c < valid) ? __expf(sv[i] - mnew) : 0.f;
                lsum += p;
                Ps[row * LDH + c] = __float2half_rn(p);
            }
            lsum += __shfl_xor_sync(0xffffffffu, lsum, 1);
            lsum += __shfl_xor_sync(0xffffffffu, lsum, 2);
            if (sub == 0) {
                mrow[row] = mnew;
                lrow[row] = lrow[row] * alpha + lsum;
            }
            #pragma unroll
            for (int i = 0; i < 16; i++) {
                int c = sub + i * 4;
                Os[row * LDH + c] *= alpha;
            }
        }
        __syncthreads();

        // O += P @ V
        {
            wmma::fragment<wmma::accumulator, 16, 16, 16, float> oc[2];
            wmma::load_matrix_sync(oc[0], &Os[wm * 16 * LDH + wn * 32],      LDH, wmma::mem_row_major);
            wmma::load_matrix_sync(oc[1], &Os[wm * 16 * LDH + wn * 32 + 16], LDH, wmma::mem_row_major);
            #pragma unroll
            for (int kk = 0; kk < 4; kk++) {
                wmma::fragment<wmma::matrix_a, 16, 16, 16, __half, wmma::row_major> a;
                wmma::load_matrix_sync(a, &Ps[wm * 16 * LDH + kk * 16], LDH);
                #pragma unroll
                for (int j = 0; j < 2; j++) {
                    wmma::fragment<wmma::matrix_b, 16, 16, 16, __half, wmma::row_major> bv;
                    wmma::load_matrix_sync(bv, &Vs[kk * 16 * LDH + wn * 32 + j * 16], LDH);
                    wmma::mma_sync(oc[j], a, bv, oc[j]);
                }
            }
            wmma::store_matrix_sync(&Os[wm * 16 * LDH + wn * 32],      oc[0], LDH, wmma::mem_row_major);
            wmma::store_matrix_sync(&Os[wm * 16 * LDH + wn * 32 + 16], oc[1], LDH, wmma::mem_row_major);
        }
    }
    __syncthreads();

    // write normalized O as half to g_Oh [b, tok, h*64+d]
    for (int i = tid; i < 4096; i += 256) {
        int r  = i >> 6;
        int d  = i & 63;
        int qi = q0 + r;
        if (qi >= SEQ) continue;
        float val = Os[r * LDH + d] / lrow[r];
        g_Oh[((size_t)(b * SEQ + qi)) * EMBED + h * HDIM + d] = __float2half_rn(val);
    }
}

// ===========================================================================
// Aux: fp32 -> fp16 conversion (vectorized, grid-stride)
// ===========================================================================
__global__ void f2h_kernel(const float* __restrict__ src, __half* __restrict__ dst,
                           size_t n8)
{
    for (size_t i = blockIdx.x * blockDim.x + threadIdx.x; i < n8;
         i += (size_t)gridDim.x * blockDim.x) {
        float4 a = ((const float4*)src)[2 * i];
        float4 b = ((const float4*)src)[2 * i + 1];
        __half2 h0 = __floats2half2_rn(a.x, a.y);
        __half2 h1 = __floats2half2_rn(a.z, a.w);
        __half2 h2 = __floats2half2_rn(b.x, b.y);
        __half2 h3 = __floats2half2_rn(b.z, b.w);
        uint4 o;
        o.x = *(uint32_t*)&h0; o.y = *(uint32_t*)&h1;
        o.z = *(uint32_t*)&h2; o.w = *(uint32_t*)&h3;
        ((uint4*)dst)[i] = o;
    }
}

// ===========================================================================
extern "C" void kernel_launch(void* const* d_in, const int* in_sizes, int n_in,
                              void* d_out, int out_size)
{
    (void)in_sizes; (void)n_in; (void)out_size;
    const float* x      = (const float*)d_in[0];
    const float* w_qkv  = (const float*)d_in[1];
    const float* w_proj = (const float*)d_in[2];
    const float* b_proj = (const float*)d_in[3];
    float* out = (float*)d_out;

    cudaFuncSetAttribute(gemm_qkv_kernel,  cudaFuncAttributeMaxDynamicSharedMemorySize, GEMM_SMEM_BYTES);
    cudaFuncSetAttribute(gemm_proj_kernel, cudaFuncAttributeMaxDynamicSharedMemorySize, GEMM_SMEM_BYTES);
    cudaFuncSetAttribute(attn_kernel,      cudaFuncAttributeMaxDynamicSharedMemorySize, (int)ATTN_SMEM);

    __half *dXh, *dWqkvh, *dWprojh, *dOh;
    cudaGetSymbolAddress((void**)&dXh,     g_Xh);
    cudaGetSymbolAddress((void**)&dWqkvh,  g_Wqkvh);
    cudaGetSymbolAddress((void**)&dWprojh, g_Wprojh);
    cudaGetSymbolAddress((void**)&dOh,     g_Oh);

    f2h_kernel<<<1184, 256>>>(x,      dXh,     (size_t)MROWS * EMBED / 8);
    f2h_kernel<<<592,  256>>>(w_qkv,  dWqkvh,  (size_t)EMBED * QKV_N / 8);
    f2h_kernel<<<296,  256>>>(w_proj, dWprojh, (size_t)EMBED * EMBED / 8);

    const int mblocks = (MROWS + BM - 1) / BM;   // 145
    gemm_qkv_kernel<<<dim3(QKV_N / BN, mblocks), 256, GEMM_SMEM_BYTES>>>(dXh, dWqkvh);
    attn_kernel<<<dim3(KV_TILES, BATCH * HEADS), 256, ATTN_SMEM>>>();
    gemm_proj_kernel<<<dim3(EMBED / BN, mblocks), 256, GEMM_SMEM_BYTES>>>(dOh, dWprojh, b_proj, out);
}

// round 6
// speedup vs baseline: 3.5076x; 1.0447x over previous
#include <cuda_runtime.h>
#include <cuda_fp16.h>
#include <mma.h>
#include <cstdint>

using namespace nvcuda;

#define BATCH   32
#define SEQ     577
#define EMBED   768
#define HEADS   12
#define HDIM    64
#define MROWS   (BATCH * SEQ)        // 18464
#define QKV_N   (3 * EMBED)          // 2304
#define ATT_SCALE 0.125f             // HDIM^-0.5

// ---------------- scratch (module-load allocated, no runtime allocs) -------
__device__ __half g_Qh[(size_t)BATCH * HEADS * SEQ * HDIM];   // [b,h,n,d], pre-scaled
__device__ __half g_Kh[(size_t)BATCH * HEADS * SEQ * HDIM];
__device__ __half g_Vh[(size_t)BATCH * HEADS * SEQ * HDIM];
__device__ __half g_Oh[(size_t)MROWS * EMBED];                // attention out (half)
__device__ __half g_Xh[(size_t)MROWS * EMBED];                // half X
__device__ __half g_Wqkvh[(size_t)EMBED * QKV_N];             // half W_qkv (row-major)
__device__ __half g_Wprojh[(size_t)EMBED * EMBED];            // half W_proj (row-major)

// ---------------- cp.async helpers ----------------------------------------
__device__ __forceinline__ uint32_t smem_u32(const void* p) {
    uint32_t a;
    asm("{ .reg .u64 t; cvta.to.shared.u64 t, %1; cvt.u32.u64 %0, t; }"
        : "=r"(a) : "l"(p));
    return a;
}
__device__ __forceinline__ void cp16(uint32_t dst, const void* src, bool pred) {
    int sz = pred ? 16 : 0;
    asm volatile("cp.async.cg.shared.global [%0], [%1], 16, %2;\n"
                 :: "r"(dst), "l"(src), "r"(sz));
}
#define CP_COMMIT() asm volatile("cp.async.commit_group;\n" ::: "memory")
#define CP_WAIT1()  asm volatile("cp.async.wait_group 1;\n" ::: "memory")
#define CP_WAIT0()  asm volatile("cp.async.wait_group 0;\n" ::: "memory")

// ---------------- GEMM tiling (fp16 mma.sync m16n16k16) --------------------
// BM=128, BN=128, BK=32; 256 threads = 8 warps as 4(m) x 2(n); warp tile 32x64.
// 3-stage cp.async pipeline, ONE __syncthreads per K-step.
#define BM 128
#define BN 128
#define BK 32
#define LDA 40                        // A smem row stride (halves)
#define LDB 136                       // B smem row stride (halves)
#define LDCc 132                      // epilogue f32 stride
#define A_STAGE (BM * LDA)            // 5120 halves
#define B_STAGE (BK * LDB)            // 4352 halves
#define KTILES (EMBED / BK)           // 24
#define GEMM_SMEM_BYTES (BM * LDCc * 4)   // 67584 (mainloop needs 56832)

__device__ __forceinline__ void gemm_mainloop_h(
    const __half* __restrict__ Ag, int lda_g, int m0, bool mtail,
    const __half* __restrict__ Bg, int ldb_g, int n0,
    __half* sm,
    wmma::fragment<wmma::accumulator, 16, 16, 16, float> (&acc)[2][4])
{
    __half* sA = sm;
    __half* sB = sm + 3 * A_STAGE;

    const int tid  = threadIdx.x;
    const int warp = tid >> 5;
    const int wm   = warp >> 1;       // 0..3
    const int wn   = warp & 1;        // 0..1

    uint32_t sA_u = smem_u32(sA);
    uint32_t sB_u = smem_u32(sB);

    auto issue = [&](int kt, int st) {
        const int k0 = kt * BK;
        // A: 128 rows x 32 halves = 512 8-half chunks -> 2/thread
        #pragma unroll
        for (int j = 0; j < 2; j++) {
            int i  = tid + j * 256;
            int r  = i >> 2;
            int ch = i & 3;
            int gm = m0 + r;
            bool p = !mtail || (gm < MROWS);
            cp16(sA_u + (uint32_t)(st * A_STAGE + r * LDA + ch * 8) * 2,
                 Ag + (size_t)gm * lda_g + k0 + ch * 8, p);
        }
        // B: 32 rows x 128 halves = 512 chunks -> 2/thread
        #pragma unroll
        for (int j = 0; j < 2; j++) {
            int i  = tid + j * 256;
            int r  = i >> 4;
            int ch = i & 15;
            cp16(sB_u + (uint32_t)(st * B_STAGE + r * LDB + ch * 8) * 2,
                 Bg + (size_t)(k0 + r) * ldb_g + n0 + ch * 8, true);
        }
        CP_COMMIT();
    };

    issue(0, 0);
    issue(1, 1);

    for (int it = 0; it < KTILES; it++) {
        if (it == KTILES - 1) CP_WAIT0(); else CP_WAIT1();
        __syncthreads();                       // data(it) visible; compute(it-1) done
        if (it + 2 < KTILES) issue(it + 2, (it + 2) % 3);

        const int st = it % 3;
        const __half* At = sA + st * A_STAGE + wm * 32 * LDA;
        const __half* Bt = sB + st * B_STAGE + wn * 64;
        #pragma unroll
        for (int kk = 0; kk < BK / 16; kk++) {
            wmma::fragment<wmma::matrix_a, 16, 16, 16, __half, wmma::row_major> a0, a1;
            wmma::load_matrix_sync(a0, At + kk * 16, LDA);
            wmma::load_matrix_sync(a1, At + 16 * LDA + kk * 16, LDA);
            #pragma unroll
            for (int j = 0; j < 4; j++) {
                wmma::fragment<wmma::matrix_b, 16, 16, 16, __half, wmma::row_major> b;
                wmma::load_matrix_sync(b, Bt + kk * 16 * LDB + j * 16, LDB);
                wmma::mma_sync(acc[0][j], a0, b, acc[0][j]);
                wmma::mma_sync(acc[1][j], a1, b, acc[1][j]);
            }
        }
    }
    __syncthreads();   // before epilogue reuses smem
}

template <typename EPI>
__device__ __forceinline__ void gemm_epilogue(
    wmma::fragment<wmma::accumulator, 16, 16, 16, float> (&acc)[2][4],
    float* Cs, EPI epi)
{
    const int tid  = threadIdx.x;
    const int warp = tid >> 5;
    const int wm   = warp >> 1;
    const int wn   = warp & 1;
    #pragma unroll
    for (int i = 0; i < 2; i++)
        #pragma unroll
        for (int j = 0; j < 4; j++)
            wmma::store_matrix_sync(&Cs[(wm * 32 + i * 16) * LDCc + wn * 64 + j * 16],
                                    acc[i][j], LDCc, wmma::mem_row_major);
    __syncthreads();
    for (int i = tid; i < BM * BN; i += 256) {
        int r = i >> 7;
        int c = i & 127;
        epi(r, c, Cs[r * LDCc + c]);
    }
}

// ===========================================================================
// Kernel 1: QKV GEMM + scatter epilogue into g_Qh/g_Kh/g_Vh (half, Q scaled)
// ===========================================================================
__global__ void __launch_bounds__(256, 2) gemm_qkv_kernel(const __half* __restrict__ X,
                                                          const __half* __restrict__ W)
{
    extern __shared__ __half smh[];
    const int m0 = blockIdx.y * BM;
    const int n0 = blockIdx.x * BN;
    const bool mtail = (m0 + BM > MROWS);

    wmma::fragment<wmma::accumulator, 16, 16, 16, float> acc[2][4];
    #pragma unroll
    for (int i = 0; i < 2; i++)
        #pragma unroll
        for (int j = 0; j < 4; j++) wmma::fill_fragment(acc[i][j], 0.0f);

    gemm_mainloop_h(X, EMBED, m0, mtail, W, QKV_N, n0, smh, acc);

    gemm_epilogue(acc, (float*)smh, [&](int r, int c, float val) {
        int gm = m0 + r;
        if (gm >= MROWS) return;
        int gn  = n0 + c;
        int b   = gm / SEQ;
        int tok = gm - b * SEQ;
        int s   = gn / EMBED;
        int rem = gn - s * EMBED;
        int h   = rem >> 6;
        int d   = rem & 63;
        size_t idx = ((size_t)(b * HEADS + h) * SEQ + tok) * HDIM + d;
        if (s == 0)      g_Qh[idx] = __float2half_rn(val * ATT_SCALE);
        else if (s == 1) g_Kh[idx] = __float2half_rn(val);
        else             g_Vh[idx] = __float2half_rn(val);
    });
}

// ===========================================================================
// Kernel 3: projection GEMM.  out = g_Oh @ Wp + bias  (fp32 out)
// ===========================================================================
__global__ void __launch_bounds__(256, 2) gemm_proj_kernel(const __half* __restrict__ A,
                                                           const __half* __restrict__ W,
                                                           const float* __restrict__ bias,
                                                           float* __restrict__ out)
{
    extern __shared__ __half smh[];
    const int m0 = blockIdx.y * BM;
    const int n0 = blockIdx.x * BN;
    const bool mtail = (m0 + BM > MROWS);

    wmma::fragment<wmma::accumulator, 16, 16, 16, float> acc[2][4];
    #pragma unroll
    for (int i = 0; i < 2; i++)
        #pragma unroll
        for (int j = 0; j < 4; j++) wmma::fill_fragment(acc[i][j], 0.0f);

    gemm_mainloop_h(A, EMBED, m0, mtail, W, EMBED, n0, smh, acc);

    gemm_epilogue(acc, (float*)smh, [&](int r, int c, float val) {
        int gm = m0 + r;
        if (gm >= MROWS) return;
        int gn = n0 + c;
        out[(size_t)gm * EMBED + gn] = val + bias[gn];
    });
}

// ===========================================================================
// Kernel 2: flash attention, fp16 MMA, double-buffered cp.async K/V.
// One block per (b,h, 64-q tile); 256 threads (8 warps, 4m x 2n over 64x64).
// ===========================================================================
#define KV_TILES ((SEQ + 63) / 64)                 // 10
#define LDH 72
#define TILE_H (64 * LDH)                          // 4608
// smem: Ss f32 + Os f32 + m/l + Qs + Ks[2] + Vs[2] + Ps (halves)
#define ATTN_SMEM ((2 * TILE_H + 128) * 4 + 6 * TILE_H * 2)   // 92672 B

__global__ void __launch_bounds__(256) attn_kernel()
{
    extern __shared__ char smraw[];
    float*  Ss   = (float*)smraw;                   // 64x72 f32
    float*  Os   = Ss + TILE_H;                     // 64x72 f32
    float*  mrow = Os + TILE_H;                     // 64
    float*  lrow = mrow + 64;                       // 64
    __half* Qs   = (__half*)(lrow + 64);            // 64x72
    __half* Ks   = Qs + TILE_H;                     // 2 stages
    __half* Vs   = Ks + 2 * TILE_H;                 // 2 stages
    __half* Ps   = Vs + 2 * TILE_H;                 // 64x72

    const int tid  = threadIdx.x;
    const int warp = tid >> 5;
    const int wm   = warp >> 1;
    const int wn   = warp & 1;
    const int bh   = blockIdx.y;
    const int b    = bh / HEADS;
    const int h    = bh - b * HEADS;
    const int q0   = blockIdx.x * 64;

    const __half* Qg = g_Qh + (size_t)bh * SEQ * HDIM;
    const __half* Kg = g_Kh + (size_t)bh * SEQ * HDIM;
    const __half* Vg = g_Vh + (size_t)bh * SEQ * HDIM;

    uint32_t Qs_u = smem_u32(Qs);
    uint32_t Ks_u = smem_u32(Ks);
    uint32_t Vs_u = smem_u32(Vs);

    auto issue_kv = [&](int kt, int st) {
        const int kbase = kt * 64;
        #pragma unroll
        for (int j = 0; j < 2; j++) {
            int i  = tid + j * 256;
            int r  = i >> 3;
            int c8 = (i & 7) << 3;
            int ki = kbase + r;
            bool p = ki < SEQ;
            uint32_t off = (uint32_t)(st * TILE_H + r * LDH + c8) * 2;
            const __half* src = Kg + (size_t)ki * HDIM + c8;
            cp16(Ks_u + off, src, p);
            cp16(Vs_u + off, Vg + (size_t)ki * HDIM + c8, p);
        }
        CP_COMMIT();
    };

    // prologue: async Q load + KV tile 0 (group 0); init Os/m/l
    #pragma unroll
    for (int j = 0; j < 2; j++) {
        int i  = tid + j * 256;
        int r  = i >> 3;
        int c8 = (i & 7) << 3;
        int qi = q0 + r;
        cp16(Qs_u + (uint32_t)(r * LDH + c8) * 2, Qg + (size_t)qi * HDIM + c8, qi < SEQ);
    }
    issue_kv(0, 0);   // commits group 0 (includes Q)

    for (int i = tid; i < 64 * 18; i += 256) {
        int r  = i / 18;
        int c4 = (i % 18) << 2;
        *(float4*)(Os + r * LDH + c4) = make_float4(0.f, 0.f, 0.f, 0.f);
    }
    if (tid < 64) { mrow[tid] = -1e30f; lrow[tid] = 0.f; }

    const int row = tid >> 2;
    const int sub = tid & 3;

    for (int kt = 0; kt < KV_TILES; kt++) {
        const int st    = kt & 1;
        const int valid = min(64, SEQ - kt * 64);

        __syncthreads();                    // PV(kt-1) done / prologue inits done
        if (kt + 1 < KV_TILES) { issue_kv(kt + 1, st ^ 1); CP_WAIT1(); }
        else                   { CP_WAIT0(); }
        __syncthreads();                    // stage st (and Q on kt==0) visible

        // S = Q @ K^T
        {
            wmma::fragment<wmma::accumulator, 16, 16, 16, float> sacc[2];
            wmma::fill_fragment(sacc[0], 0.0f);
            wmma::fill_fragment(sacc[1], 0.0f);
            const __half* Kt = Ks + st * TILE_H;
            #pragma unroll
            for (int kk = 0; kk < HDIM / 16; kk++) {
                wmma::fragment<wmma::matrix_a, 16, 16, 16, __half, wmma::row_major> a;
                wmma::load_matrix_sync(a, &Qs[wm * 16 * LDH + kk * 16], LDH);
                #pragma unroll
                for (int j = 0; j < 2; j++) {
                    wmma::fragment<wmma::matrix_b, 16, 16, 16, __half, wmma::col_major> bk;
                    wmma::load_matrix_sync(bk, &Kt[(wn * 32 + j * 16) * LDH + kk * 16], LDH);
                    wmma::mma_sync(sacc[j], a, bk, sacc[j]);
                }
            }
            wmma::store_matrix_sync(&Ss[wm * 16 * LDH + wn * 32],      sacc[0], LDH, wmma::mem_row_major);
            wmma::store_matrix_sync(&Ss[wm * 16 * LDH + wn * 32 + 16], sacc[1], LDH, wmma::mem_row_major);
        }
        __syncthreads();

        // online softmax (4 threads/row)
        {
            float sv[16];
            float mloc = -1e30f;
            #pragma unroll
            for (int i = 0; i < 16; i++) {
                int c = sub + i * 4;
                float s = (c < valid) ? Ss[row * LDH + c] : -1e30f;
                sv[i] = s;
                mloc = fmaxf(mloc, s);
            }
            mloc = fmaxf(mloc, __shfl_xor_sync(0xffffffffu, mloc, 1));
            mloc = fmaxf(mloc, __shfl_xor_sync(0xffffffffu, mloc, 2));
            float mold = mrow[row];
            float mnew = fmaxf(mold, mloc);
            float alpha = __expf(mold - mnew);
            float lsum = 0.f;
            #pragma unroll
            for (int i = 0; i < 16; i++) {
                int c = sub + i * 4;
                float p = (c < valid) ? __expf(sv[i] - mnew) : 0.f;
                lsum += p;
                Ps[row * LDH + c] = __float2half_rn(p);
            }
            lsum += __shfl_xor_sync(0xffffffffu, lsum, 1);
            lsum += __shfl_xor_sync(0xffffffffu, lsum, 2);
            if (sub == 0) {
                mrow[row] = mnew;
                lrow[row] = lrow[row] * alpha + lsum;
            }
            #pragma unroll
            for (int i = 0; i < 16; i++) {
                int c = sub + i * 4;
                Os[row * LDH + c] *= alpha;
            }
        }
        __syncthreads();

        // O += P @ V
        {
            wmma::fragment<wmma::accumulator, 16, 16, 16, float> oc[2];
            wmma::load_matrix_sync(oc[0], &Os[wm * 16 * LDH + wn * 32],      LDH, wmma::mem_row_major);
            wmma::load_matrix_sync(oc[1], &Os[wm * 16 * LDH + wn * 32 + 16], LDH, wmma::mem_row_major);
            const __half* Vt = Vs + st * TILE_H;
            #pragma unroll
            for (int kk = 0; kk < 4; kk++) {
                wmma::fragment<wmma::matrix_a, 16, 16, 16, __half, wmma::row_major> a;
                wmma::load_matrix_sync(a, &Ps[wm * 16 * LDH + kk * 16], LDH);
                #pragma unroll
                for (int j = 0; j < 2; j++) {
                    wmma::fragment<wmma::matrix_b, 16, 16, 16, __half, wmma::row_major> bv;
                    wmma::load_matrix_sync(bv, &Vt[kk * 16 * LDH + wn * 32 + j * 16], LDH);
                    wmma::mma_sync(oc[j], a, bv, oc[j]);
                }
            }
            wmma::store_matrix_sync(&Os[wm * 16 * LDH + wn * 32],      oc[0], LDH, wmma::mem_row_major);
            wmma::store_matrix_sync(&Os[wm * 16 * LDH + wn * 32 + 16], oc[1], LDH, wmma::mem_row_major);
        }
    }
    __syncthreads();

    // write normalized O as half to g_Oh [b, tok, h*64+d]
    for (int i = tid; i < 4096; i += 256) {
        int r  = i >> 6;
        int d  = i & 63;
        int qi = q0 + r;
        if (qi >= SEQ) continue;
        float val = Os[r * LDH + d] / lrow[r];
        g_Oh[((size_t)(b * SEQ + qi)) * EMBED + h * HDIM + d] = __float2half_rn(val);
    }
}

// ===========================================================================
// Aux: fp32 -> fp16 conversion (vectorized, grid-stride)
// ===========================================================================
__global__ void f2h_kernel(const float* __restrict__ src, __half* __restrict__ dst,
                           size_t n8)
{
    for (size_t i = blockIdx.x * blockDim.x + threadIdx.x; i < n8;
         i += (size_t)gridDim.x * blockDim.x) {
        float4 a = ((const float4*)src)[2 * i];
        float4 b = ((const float4*)src)[2 * i + 1];
        __half2 h0 = __floats2half2_rn(a.x, a.y);
        __half2 h1 = __floats2half2_rn(a.z, a.w);
        __half2 h2 = __floats2half2_rn(b.x, b.y);
        __half2 h3 = __floats2half2_rn(b.z, b.w);
        uint4 o;
        o.x = *(uint32_t*)&h0; o.y = *(uint32_t*)&h1;
        o.z = *(uint32_t*)&h2; o.w = *(uint32_t*)&h3;
        ((uint4*)dst)[i] = o;
    }
}

// ===========================================================================
extern "C" void kernel_launch(void* const* d_in, const int* in_sizes, int n_in,
                              void* d_out, int out_size)
{
    (void)in_sizes; (void)n_in; (void)out_size;
    const float* x      = (const float*)d_in[0];
    const float* w_qkv  = (const float*)d_in[1];
    const float* w_proj = (const float*)d_in[2];
    const float* b_proj = (const float*)d_in[3];
    float* out = (float*)d_out;

    cudaFuncSetAttribute(gemm_qkv_kernel,  cudaFuncAttributeMaxDynamicSharedMemorySize, GEMM_SMEM_BYTES);
    cudaFuncSetAttribute(gemm_proj_kernel, cudaFuncAttributeMaxDynamicSharedMemorySize, GEMM_SMEM_BYTES);
    cudaFuncSetAttribute(attn_kernel,      cudaFuncAttributeMaxDynamicSharedMemorySize, (int)ATTN_SMEM);

    __half *dXh, *dWqkvh, *dWprojh, *dOh;
    cudaGetSymbolAddress((void**)&dXh,     g_Xh);
    cudaGetSymbolAddress((void**)&dWqkvh,  g_Wqkvh);
    cudaGetSymbolAddress((void**)&dWprojh, g_Wprojh);
    cudaGetSymbolAddress((void**)&dOh,     g_Oh);

    f2h_kernel<<<1184, 256>>>(x,      dXh,     (size_t)MROWS * EMBED / 8);
    f2h_kernel<<<592,  256>>>(w_qkv,  dWqkvh,  (size_t)EMBED * QKV_N / 8);
    f2h_kernel<<<296,  256>>>(w_proj, dWprojh, (size_t)EMBED * EMBED / 8);

    const int mblocks = (MROWS + BM - 1) / BM;   // 145
    gemm_qkv_kernel<<<dim3(QKV_N / BN, mblocks), 256, GEMM_SMEM_BYTES>>>(dXh, dWqkvh);
    attn_kernel<<<dim3(KV_TILES, BATCH * HEADS), 256, ATTN_SMEM>>>();
    gemm_proj_kernel<<<dim3(EMBED / BN, mblocks), 256, GEMM_SMEM_BYTES>>>(dOh, dWprojh, b_proj, out);
}

// round 7
// speedup vs baseline: 4.9903x; 1.4227x over previous
#include <cuda_runtime.h>
#include <cuda_fp16.h>
#include <mma.h>
#include <cstdint>

using namespace nvcuda;

#define BATCH   32
#define SEQ     577
#define EMBED   768
#define HEADS   12
#define HDIM    64
#define MROWS   (BATCH * SEQ)        // 18464
#define QKV_N   (3 * EMBED)          // 2304
#define ATT_SCALE 0.125f             // HDIM^-0.5

// ---------------- scratch (module-load allocated, no runtime allocs) -------
__device__ __half g_Qh[(size_t)BATCH * HEADS * SEQ * HDIM];   // [b,h,n,d], pre-scaled
__device__ __half g_Kh[(size_t)BATCH * HEADS * SEQ * HDIM];
__device__ __half g_Vh[(size_t)BATCH * HEADS * SEQ * HDIM];
__device__ __half g_Oh[(size_t)MROWS * EMBED];                // attention out (half)
__device__ __half g_Xh[(size_t)MROWS * EMBED];                // half X
__device__ __half g_Wqkvh[(size_t)EMBED * QKV_N];             // half W_qkv (row-major)
__device__ __half g_Wprojh[(size_t)EMBED * EMBED];            // half W_proj (row-major)

// ---------------- PTX helpers ----------------------------------------------
__device__ __forceinline__ uint32_t smem_u32(const void* p) {
    uint32_t a;
    asm("{ .reg .u64 t; cvta.to.shared.u64 t, %1; cvt.u32.u64 %0, t; }"
        : "=r"(a) : "l"(p));
    return a;
}
__device__ __forceinline__ void cp16(uint32_t dst, const void* src, bool pred) {
    int sz = pred ? 16 : 0;
    asm volatile("cp.async.cg.shared.global [%0], [%1], 16, %2;\n"
                 :: "r"(dst), "l"(src), "r"(sz));
}
#define CP_COMMIT() asm volatile("cp.async.commit_group;\n" ::: "memory")
#define CP_WAIT1()  asm volatile("cp.async.wait_group 1;\n" ::: "memory")
#define CP_WAIT0()  asm volatile("cp.async.wait_group 0;\n" ::: "memory")

__device__ __forceinline__ void ldsm_x4(uint32_t (&r)[4], uint32_t addr) {
    asm volatile("ldmatrix.sync.aligned.m8n8.x4.shared.b16 {%0,%1,%2,%3}, [%4];"
                 : "=r"(r[0]), "=r"(r[1]), "=r"(r[2]), "=r"(r[3]) : "r"(addr));
}
__device__ __forceinline__ void ldsm_x2(uint32_t& r0, uint32_t& r1, uint32_t addr) {
    asm volatile("ldmatrix.sync.aligned.m8n8.x2.shared.b16 {%0,%1}, [%2];"
                 : "=r"(r0), "=r"(r1) : "r"(addr));
}
__device__ __forceinline__ void ldsm_x2t(uint32_t& r0, uint32_t& r1, uint32_t addr) {
    asm volatile("ldmatrix.sync.aligned.m8n8.x2.trans.shared.b16 {%0,%1}, [%2];"
                 : "=r"(r0), "=r"(r1) : "r"(addr));
}
__device__ __forceinline__ void mma16816(float (&d)[4], const uint32_t (&a)[4],
                                         uint32_t b0, uint32_t b1) {
    asm volatile("mma.sync.aligned.m16n8k16.row.col.f32.f16.f16.f32 "
                 "{%0,%1,%2,%3}, {%4,%5,%6,%7}, {%8,%9}, {%0,%1,%2,%3};"
                 : "+f"(d[0]), "+f"(d[1]), "+f"(d[2]), "+f"(d[3])
                 : "r"(a[0]), "r"(a[1]), "r"(a[2]), "r"(a[3]), "r"(b0), "r"(b1));
}

// ---------------- GEMM tiling (fp16 mma.sync m16n16k16) — unchanged R6 -----
#define BM 128
#define BN 128
#define BK 32
#define LDA 40
#define LDB 136
#define LDCc 132
#define A_STAGE (BM * LDA)
#define B_STAGE (BK * LDB)
#define KTILES (EMBED / BK)
#define GEMM_SMEM_BYTES (BM * LDCc * 4)

__device__ __forceinline__ void gemm_mainloop_h(
    const __half* __restrict__ Ag, int lda_g, int m0, bool mtail,
    const __half* __restrict__ Bg, int ldb_g, int n0,
    __half* sm,
    wmma::fragment<wmma::accumulator, 16, 16, 16, float> (&acc)[2][4])
{
    __half* sA = sm;
    __half* sB = sm + 3 * A_STAGE;

    const int tid  = threadIdx.x;
    const int warp = tid >> 5;
    const int wm   = warp >> 1;
    const int wn   = warp & 1;

    uint32_t sA_u = smem_u32(sA);
    uint32_t sB_u = smem_u32(sB);

    auto issue = [&](int kt, int st) {
        const int k0 = kt * BK;
        #pragma unroll
        for (int j = 0; j < 2; j++) {
            int i  = tid + j * 256;
            int r  = i >> 2;
            int ch = i & 3;
            int gm = m0 + r;
            bool p = !mtail || (gm < MROWS);
            cp16(sA_u + (uint32_t)(st * A_STAGE + r * LDA + ch * 8) * 2,
                 Ag + (size_t)gm * lda_g + k0 + ch * 8, p);
        }
        #pragma unroll
        for (int j = 0; j < 2; j++) {
            int i  = tid + j * 256;
            int r  = i >> 4;
            int ch = i & 15;
            cp16(sB_u + (uint32_t)(st * B_STAGE + r * LDB + ch * 8) * 2,
                 Bg + (size_t)(k0 + r) * ldb_g + n0 + ch * 8, true);
        }
        CP_COMMIT();
    };

    issue(0, 0);
    issue(1, 1);

    for (int it = 0; it < KTILES; it++) {
        if (it == KTILES - 1) CP_WAIT0(); else CP_WAIT1();
        __syncthreads();
        if (it + 2 < KTILES) issue(it + 2, (it + 2) % 3);

        const int st = it % 3;
        const __half* At = sA + st * A_STAGE + wm * 32 * LDA;
        const __half* Bt = sB + st * B_STAGE + wn * 64;
        #pragma unroll
        for (int kk = 0; kk < BK / 16; kk++) {
            wmma::fragment<wmma::matrix_a, 16, 16, 16, __half, wmma::row_major> a0, a1;
            wmma::load_matrix_sync(a0, At + kk * 16, LDA);
            wmma::load_matrix_sync(a1, At + 16 * LDA + kk * 16, LDA);
            #pragma unroll
            for (int j = 0; j < 4; j++) {
                wmma::fragment<wmma::matrix_b, 16, 16, 16, __half, wmma::row_major> b;
                wmma::load_matrix_sync(b, Bt + kk * 16 * LDB + j * 16, LDB);
                wmma::mma_sync(acc[0][j], a0, b, acc[0][j]);
                wmma::mma_sync(acc[1][j], a1, b, acc[1][j]);
            }
        }
    }
    __syncthreads();
}

template <typename EPI>
__device__ __forceinline__ void gemm_epilogue(
    wmma::fragment<wmma::accumulator, 16, 16, 16, float> (&acc)[2][4],
    float* Cs, EPI epi)
{
    const int tid  = threadIdx.x;
    const int warp = tid >> 5;
    const int wm   = warp >> 1;
    const int wn   = warp & 1;
    #pragma unroll
    for (int i = 0; i < 2; i++)
        #pragma unroll
        for (int j = 0; j < 4; j++)
            wmma::store_matrix_sync(&Cs[(wm * 32 + i * 16) * LDCc + wn * 64 + j * 16],
                                    acc[i][j], LDCc, wmma::mem_row_major);
    __syncthreads();
    for (int i = tid; i < BM * BN; i += 256) {
        int r = i >> 7;
        int c = i & 127;
        epi(r, c, Cs[r * LDCc + c]);
    }
}

// ===========================================================================
// Kernel 1: QKV GEMM + scatter epilogue (unchanged R6)
// ===========================================================================
__global__ void __launch_bounds__(256, 2) gemm_qkv_kernel(const __half* __restrict__ X,
                                                          const __half* __restrict__ W)
{
    extern __shared__ __half smh[];
    const int m0 = blockIdx.y * BM;
    const int n0 = blockIdx.x * BN;
    const bool mtail = (m0 + BM > MROWS);

    wmma::fragment<wmma::accumulator, 16, 16, 16, float> acc[2][4];
    #pragma unroll
    for (int i = 0; i < 2; i++)
        #pragma unroll
        for (int j = 0; j < 4; j++) wmma::fill_fragment(acc[i][j], 0.0f);

    gemm_mainloop_h(X, EMBED, m0, mtail, W, QKV_N, n0, smh, acc);

    gemm_epilogue(acc, (float*)smh, [&](int r, int c, float val) {
        int gm = m0 + r;
        if (gm >= MROWS) return;
        int gn  = n0 + c;
        int b   = gm / SEQ;
        int tok = gm - b * SEQ;
        int s   = gn / EMBED;
        int rem = gn - s * EMBED;
        int h   = rem >> 6;
        int d   = rem & 63;
        size_t idx = ((size_t)(b * HEADS + h) * SEQ + tok) * HDIM + d;
        if (s == 0)      g_Qh[idx] = __float2half_rn(val * ATT_SCALE);
        else if (s == 1) g_Kh[idx] = __float2half_rn(val);
        else             g_Vh[idx] = __float2half_rn(val);
    });
}

// ===========================================================================
// Kernel 3: projection GEMM (unchanged R6)
// ===========================================================================
__global__ void __launch_bounds__(256, 2) gemm_proj_kernel(const __half* __restrict__ A,
                                                           const __half* __restrict__ W,
                                                           const float* __restrict__ bias,
                                                           float* __restrict__ out)
{
    extern __shared__ __half smh[];
    const int m0 = blockIdx.y * BM;
    const int n0 = blockIdx.x * BN;
    const bool mtail = (m0 + BM > MROWS);

    wmma::fragment<wmma::accumulator, 16, 16, 16, float> acc[2][4];
    #pragma unroll
    for (int i = 0; i < 2; i++)
        #pragma unroll
        for (int j = 0; j < 4; j++) wmma::fill_fragment(acc[i][j], 0.0f);

    gemm_mainloop_h(A, EMBED, m0, mtail, W, EMBED, n0, smh, acc);

    gemm_epilogue(acc, (float*)smh, [&](int r, int c, float val) {
        int gm = m0 + r;
        if (gm >= MROWS) return;
        int gn = n0 + c;
        out[(size_t)gm * EMBED + gn] = val + bias[gn];
    });
}

// ===========================================================================
// Kernel 2: flash attention, FA2-style: raw mma.m16n8k16, register softmax/O.
// Block = 128 q rows (8 warps x 16 rows), KV tiles of 64, double-buffered.
// ===========================================================================
#define KV_TILES ((SEQ + 63) / 64)                 // 10
#define LDH 72
#define KV_TILE_H (64 * LDH)                       // halves per K/V stage
#define Q_TILE_H  (128 * LDH)
#define ATTN_SMEM ((Q_TILE_H + 4 * KV_TILE_H) * 2) // 55296 B

__global__ void __launch_bounds__(256) attn_kernel()
{
    extern __shared__ __half smh[];
    __half* Qs = smh;                    // 128 x 72
    __half* Ks = Qs + Q_TILE_H;          // 2 stages x 64 x 72
    __half* Vs = Ks + 2 * KV_TILE_H;     // 2 stages x 64 x 72

    const int tid  = threadIdx.x;
    const int warp = tid >> 5;
    const int lane = tid & 31;
    const int bh   = blockIdx.y;
    const int b    = bh / HEADS;
    const int h    = bh - b * HEADS;
    const int q0   = blockIdx.x * 128;

    const __half* Qg = g_Qh + (size_t)bh * SEQ * HDIM;
    const __half* Kg = g_Kh + (size_t)bh * SEQ * HDIM;
    const __half* Vg = g_Vh + (size_t)bh * SEQ * HDIM;

    uint32_t Qs_u = smem_u32(Qs);
    uint32_t Ks_u = smem_u32(Ks);
    uint32_t Vs_u = smem_u32(Vs);

    auto issue_kv = [&](int kt, int st) {
        const int kbase = kt * 64;
        #pragma unroll
        for (int j = 0; j < 2; j++) {
            int i  = tid + j * 256;
            int r  = i >> 3;
            int c8 = (i & 7) << 3;
            int ki = kbase + r;
            bool p = ki < SEQ;
            uint32_t off = (uint32_t)(st * KV_TILE_H + r * LDH + c8) * 2;
            cp16(Ks_u + off, Kg + (size_t)ki * HDIM + c8, p);
            cp16(Vs_u + off, Vg + (size_t)ki * HDIM + c8, p);
        }
        CP_COMMIT();
    };

    // prologue: Q (128x64) + KV tile 0 in one group
    #pragma unroll
    for (int j = 0; j < 4; j++) {
        int i  = tid + j * 256;
        int r  = i >> 3;
        int c8 = (i & 7) << 3;
        int qi = q0 + r;
        cp16(Qs_u + (uint32_t)(r * LDH + c8) * 2, Qg + (size_t)qi * HDIM + c8, qi < SEQ);
    }
    issue_kv(0, 0);

    CP_WAIT0();
    __syncthreads();

    // Q fragments: 4 k-tiles of 16x16 per warp
    uint32_t qa[4][4];
    {
        const int l8  = lane & 7;
        const int sel = lane >> 3;
        #pragma unroll
        for (int kk = 0; kk < 4; kk++) {
            uint32_t addr = Qs_u +
                (uint32_t)((warp * 16 + (sel & 1) * 8 + l8) * LDH + kk * 16 + (sel >> 1) * 8) * 2;
            ldsm_x4(qa[kk], addr);
        }
    }
    if (KV_TILES > 1) issue_kv(1, 1);

    float o[8][4];
    #pragma unroll
    for (int j = 0; j < 8; j++)
        #pragma unroll
        for (int c = 0; c < 4; c++) o[j][c] = 0.f;
    float mrow[2] = {-1e30f, -1e30f};
    float lrow[2] = {0.f, 0.f};

    const int l16 = lane & 15;

    for (int kt = 0; kt < KV_TILES; kt++) {
        const int st = kt & 1;
        if (kt > 0) {
            CP_WAIT0();
            __syncthreads();
            if (kt + 1 < KV_TILES) issue_kv(kt + 1, st ^ 1);
        }
        const uint32_t Kt_u = Ks_u + (uint32_t)(st * KV_TILE_H) * 2;
        const uint32_t Vt_u = Vs_u + (uint32_t)(st * KV_TILE_H) * 2;

        // ---- S = Q @ K^T : 8 n-tiles (kv) x 4 k-steps (d) -----------------
        float s[8][4];
        #pragma unroll
        for (int j = 0; j < 8; j++)
            #pragma unroll
            for (int c = 0; c < 4; c++) s[j][c] = 0.f;

        #pragma unroll
        for (int kk = 0; kk < 4; kk++) {
            #pragma unroll
            for (int j = 0; j < 8; j++) {
                uint32_t b0, b1;
                uint32_t addr = Kt_u +
                    (uint32_t)((j * 8 + (l16 & 7)) * LDH + kk * 16 + (l16 >> 3) * 8) * 2;
                ldsm_x2(b0, b1, addr);
                mma16816(s[j], qa[kk], b0, b1);
            }
        }

        // ---- mask + online softmax (all in registers) ---------------------
        const int kvbase = kt * 64;
        const int kvc = kvbase + 2 * (lane & 3);
        float mx0 = mrow[0], mx1 = mrow[1];
        #pragma unroll
        for (int j = 0; j < 8; j++) {
            int kv = kvc + j * 8;
            if (kv     >= SEQ) { s[j][0] = -1e30f; s[j][2] = -1e30f; }
            if (kv + 1 >= SEQ) { s[j][1] = -1e30f; s[j][3] = -1e30f; }
            mx0 = fmaxf(mx0, fmaxf(s[j][0], s[j][1]));
            mx1 = fmaxf(mx1, fmaxf(s[j][2], s[j][3]));
        }
        mx0 = fmaxf(mx0, __shfl_xor_sync(0xffffffffu, mx0, 1));
        mx0 = fmaxf(mx0, __shfl_xor_sync(0xffffffffu, mx0, 2));
        mx1 = fmaxf(mx1, __shfl_xor_sync(0xffffffffu, mx1, 1));
        mx1 = fmaxf(mx1, __shfl_xor_sync(0xffffffffu, mx1, 2));

        const float alpha0 = __expf(mrow[0] - mx0);
        const float alpha1 = __expf(mrow[1] - mx1);
        mrow[0] = mx0; mrow[1] = mx1;

        float ls0 = 0.f, ls1 = 0.f;
        uint32_t pa[4][4];
        #pragma unroll
        for (int j = 0; j < 8; j++) {
            float p0 = __expf(s[j][0] - mx0);
            float p1 = __expf(s[j][1] - mx0);
            float p2 = __expf(s[j][2] - mx1);
            float p3 = __expf(s[j][3] - mx1);
            ls0 += p0 + p1;
            ls1 += p2 + p3;
            __half2 h01 = __floats2half2_rn(p0, p1);
            __half2 h23 = __floats2half2_rn(p2, p3);
            pa[j >> 1][(j & 1) * 2 + 0] = *(uint32_t*)&h01;
            pa[j >> 1][(j & 1) * 2 + 1] = *(uint32_t*)&h23;
        }
        ls0 += __shfl_xor_sync(0xffffffffu, ls0, 1);
        ls0 += __shfl_xor_sync(0xffffffffu, ls0, 2);
        ls1 += __shfl_xor_sync(0xffffffffu, ls1, 1);
        ls1 += __shfl_xor_sync(0xffffffffu, ls1, 2);
        lrow[0] = lrow[0] * alpha0 + ls0;
        lrow[1] = lrow[1] * alpha1 + ls1;

        #pragma unroll
        for (int j = 0; j < 8; j++) {
            o[j][0] *= alpha0; o[j][1] *= alpha0;
            o[j][2] *= alpha1; o[j][3] *= alpha1;
        }

        // ---- O += P @ V : 4 k-steps (kv) x 8 n-tiles (d) ------------------
        #pragma unroll
        for (int kk = 0; kk < 4; kk++) {
            #pragma unroll
            for (int j = 0; j < 8; j++) {
                uint32_t b0, b1;
                uint32_t addr = Vt_u + (uint32_t)((kk * 16 + l16) * LDH + j * 8) * 2;
                ldsm_x2t(b0, b1, addr);
                mma16816(o[j], pa[kk], b0, b1);
            }
        }
    }

    // ---- write normalized O as half to g_Oh [b, tok, h*64+d] --------------
    const float rinv0 = 1.0f / lrow[0];
    const float rinv1 = 1.0f / lrow[1];
    const int qi0 = q0 + warp * 16 + (lane >> 2);
    const int qi1 = qi0 + 8;
    const int dbase = h * HDIM + 2 * (lane & 3);
    #pragma unroll
    for (int j = 0; j < 8; j++) {
        int d = dbase + j * 8;
        if (qi0 < SEQ) {
            __half2 v = __floats2half2_rn(o[j][0] * rinv0, o[j][1] * rinv0);
            *(__half2*)(g_Oh + (size_t)(b * SEQ + qi0) * EMBED + d) = v;
        }
        if (qi1 < SEQ) {
            __half2 v = __floats2half2_rn(o[j][2] * rinv1, o[j][3] * rinv1);
            *(__half2*)(g_Oh + (size_t)(b * SEQ + qi1) * EMBED + d) = v;
        }
    }
}

// ===========================================================================
// Aux: fp32 -> fp16 conversion (vectorized, grid-stride)
// ===========================================================================
__global__ void f2h_kernel(const float* __restrict__ src, __half* __restrict__ dst,
                           size_t n8)
{
    for (size_t i = blockIdx.x * blockDim.x + threadIdx.x; i < n8;
         i += (size_t)gridDim.x * blockDim.x) {
        float4 a = ((const float4*)src)[2 * i];
        float4 b = ((const float4*)src)[2 * i + 1];
        __half2 h0 = __floats2half2_rn(a.x, a.y);
        __half2 h1 = __floats2half2_rn(a.z, a.w);
        __half2 h2 = __floats2half2_rn(b.x, b.y);
        __half2 h3 = __floats2half2_rn(b.z, b.w);
        uint4 o;
        o.x = *(uint32_t*)&h0; o.y = *(uint32_t*)&h1;
        o.z = *(uint32_t*)&h2; o.w = *(uint32_t*)&h3;
        ((uint4*)dst)[i] = o;
    }
}

// ===========================================================================
extern "C" void kernel_launch(void* const* d_in, const int* in_sizes, int n_in,
                              void* d_out, int out_size)
{
    (void)in_sizes; (void)n_in; (void)out_size;
    const float* x      = (const float*)d_in[0];
    const float* w_qkv  = (const float*)d_in[1];
    const float* w_proj = (const float*)d_in[2];
    const float* b_proj = (const float*)d_in[3];
    float* out = (float*)d_out;

    cudaFuncSetAttribute(gemm_qkv_kernel,  cudaFuncAttributeMaxDynamicSharedMemorySize, GEMM_SMEM_BYTES);
    cudaFuncSetAttribute(gemm_proj_kernel, cudaFuncAttributeMaxDynamicSharedMemorySize, GEMM_SMEM_BYTES);
    cudaFuncSetAttribute(attn_kernel,      cudaFuncAttributeMaxDynamicSharedMemorySize, (int)ATTN_SMEM);

    __half *dXh, *dWqkvh, *dWprojh, *dOh;
    cudaGetSymbolAddress((void**)&dXh,     g_Xh);
    cudaGetSymbolAddress((void**)&dWqkvh,  g_Wqkvh);
    cudaGetSymbolAddress((void**)&dWprojh, g_Wprojh);
    cudaGetSymbolAddress((void**)&dOh,     g_Oh);

    f2h_kernel<<<1184, 256>>>(x,      dXh,     (size_t)MROWS * EMBED / 8);
    f2h_kernel<<<592,  256>>>(w_qkv,  dWqkvh,  (size_t)EMBED * QKV_N / 8);
    f2h_kernel<<<296,  256>>>(w_proj, dWprojh, (size_t)EMBED * EMBED / 8);

    const int mblocks = (MROWS + BM - 1) / BM;   // 145
    gemm_qkv_kernel<<<dim3(QKV_N / BN, mblocks), 256, GEMM_SMEM_BYTES>>>(dXh, dWqkvh);

    const int qblocks = (SEQ + 127) / 128;       // 5
    attn_kernel<<<dim3(qblocks, BATCH * HEADS), 256, ATTN_SMEM>>>();

    gemm_proj_kernel<<<dim3(EMBED / BN, mblocks), 256, GEMM_SMEM_BYTES>>>(dOh, dWprojh, b_proj, out);
}

// round 8
// speedup vs baseline: 5.7143x; 1.1451x over previous
#include <cuda_runtime.h>
#include <cuda_fp16.h>
#include <cstdint>

#define BATCH   32
#define SEQ     577
#define EMBED   768
#define HEADS   12
#define HDIM    64
#define MROWS   (BATCH * SEQ)        // 18464
#define QKV_N   (3 * EMBED)          // 2304
#define ATT_SCALE 0.125f             // HDIM^-0.5

// ---------------- scratch (module-load allocated, no runtime allocs) -------
__device__ __half g_Qh[(size_t)BATCH * HEADS * SEQ * HDIM];   // [b,h,n,d], pre-scaled
__device__ __half g_Kh[(size_t)BATCH * HEADS * SEQ * HDIM];
__device__ __half g_Vh[(size_t)BATCH * HEADS * SEQ * HDIM];
__device__ __half g_Oh[(size_t)MROWS * EMBED];                // attention out (half)
__device__ __half g_Xh[(size_t)MROWS * EMBED];                // half X
__device__ __half g_Wqkvh[(size_t)EMBED * QKV_N];             // half W_qkv (row-major)
__device__ __half g_Wprojh[(size_t)EMBED * EMBED];            // half W_proj (row-major)

// ---------------- PTX helpers ----------------------------------------------
__device__ __forceinline__ uint32_t smem_u32(const void* p) {
    uint32_t a;
    asm("{ .reg .u64 t; cvta.to.shared.u64 t, %1; cvt.u32.u64 %0, t; }"
        : "=r"(a) : "l"(p));
    return a;
}
__device__ __forceinline__ void cp16(uint32_t dst, const void* src, bool pred) {
    int sz = pred ? 16 : 0;
    asm volatile("cp.async.cg.shared.global [%0], [%1], 16, %2;\n"
                 :: "r"(dst), "l"(src), "r"(sz));
}
#define CP_COMMIT() asm volatile("cp.async.commit_group;\n" ::: "memory")
#define CP_WAIT1()  asm volatile("cp.async.wait_group 1;\n" ::: "memory")
#define CP_WAIT0()  asm volatile("cp.async.wait_group 0;\n" ::: "memory")

__device__ __forceinline__ void ldsm_x4(uint32_t (&r)[4], uint32_t addr) {
    asm volatile("ldmatrix.sync.aligned.m8n8.x4.shared.b16 {%0,%1,%2,%3}, [%4];"
                 : "=r"(r[0]), "=r"(r[1]), "=r"(r[2]), "=r"(r[3]) : "r"(addr));
}
__device__ __forceinline__ void ldsm_x4t(uint32_t (&r)[4], uint32_t addr) {
    asm volatile("ldmatrix.sync.aligned.m8n8.x4.trans.shared.b16 {%0,%1,%2,%3}, [%4];"
                 : "=r"(r[0]), "=r"(r[1]), "=r"(r[2]), "=r"(r[3]) : "r"(addr));
}
__device__ __forceinline__ void ldsm_x2(uint32_t& r0, uint32_t& r1, uint32_t addr) {
    asm volatile("ldmatrix.sync.aligned.m8n8.x2.shared.b16 {%0,%1}, [%2];"
                 : "=r"(r0), "=r"(r1) : "r"(addr));
}
__device__ __forceinline__ void ldsm_x2t(uint32_t& r0, uint32_t& r1, uint32_t addr) {
    asm volatile("ldmatrix.sync.aligned.m8n8.x2.trans.shared.b16 {%0,%1}, [%2];"
                 : "=r"(r0), "=r"(r1) : "r"(addr));
}
__device__ __forceinline__ void mma16816(float (&d)[4], const uint32_t (&a)[4],
                                         uint32_t b0, uint32_t b1) {
    asm volatile("mma.sync.aligned.m16n8k16.row.col.f32.f16.f16.f32 "
                 "{%0,%1,%2,%3}, {%4,%5,%6,%7}, {%8,%9}, {%0,%1,%2,%3};"
                 : "+f"(d[0]), "+f"(d[1]), "+f"(d[2]), "+f"(d[3])
                 : "r"(a[0]), "r"(a[1]), "r"(a[2]), "r"(a[3]), "r"(b0), "r"(b1));
}

// ---------------- GEMM tiling (raw mma, fp16) -------------------------------
// BM=128, BN=128, BK=32; 256 threads = 8 warps as 2(m) x 4(n); warp tile 64x32.
// A: padded rows (40 halves) — ldsm bank-stride 20, conflict-free.
// B: 32 rows x 16 chunks(16B), chunk swizize c^(r&7) — conflict-free trans ldsm.
// Epilogue: direct register->global stores (no smem round-trip).
#define BM 128
#define BN 128
#define BK 32
#define LDA 40
#define A_ST (BM * LDA)              // halves per A stage (5120)
#define B_ST_B 8192                  // bytes per B stage
#define KTILES (EMBED / BK)          // 24
#define GEMM_SMEM_BYTES (3 * (A_ST * 2 + B_ST_B))   // 55296

template <typename EPI>
__device__ __forceinline__ void gemm_mma(
    const __half* __restrict__ Ag, const __half* __restrict__ Bg, int ldb_g,
    int m0, int n0, bool mtail, EPI epi)
{
    extern __shared__ __half smh[];
    __half* sA = smh;
    uint32_t sA_u = smem_u32(sA);
    uint32_t sB_u = sA_u + 3 * A_ST * 2;

    const int tid  = threadIdx.x;
    const int warp = tid >> 5;
    const int lane = tid & 31;
    const int wm   = warp >> 2;      // 0..1
    const int wn   = warp & 3;       // 0..3

    auto issue = [&](int kt, int st) {
        const int k0 = kt * BK;
        // A: 128 rows x 4 chunks -> 2/thread
        #pragma unroll
        for (int j = 0; j < 2; j++) {
            int i  = tid + j * 256;
            int r  = i >> 2;
            int ch = i & 3;
            int gm = m0 + r;
            bool p = !mtail || (gm < MROWS);
            cp16(sA_u + (uint32_t)(st * A_ST + r * LDA + ch * 8) * 2,
                 Ag + (size_t)gm * EMBED + k0 + ch * 8, p);
        }
        // B: 32 rows x 16 chunks -> 2/thread, swizzled
        #pragma unroll
        for (int j = 0; j < 2; j++) {
            int i  = tid + j * 256;
            int r  = i >> 4;
            int c  = i & 15;
            cp16(sB_u + (uint32_t)(st * B_ST_B + r * 256 + ((c ^ (r & 7)) << 4)),
                 Bg + (size_t)(k0 + r) * ldb_g + n0 + c * 8, true);
        }
        CP_COMMIT();
    };

    float acc[4][4][4];
    #pragma unroll
    for (int i = 0; i < 4; i++)
        #pragma unroll
        for (int j = 0; j < 4; j++)
            #pragma unroll
            for (int c = 0; c < 4; c++) acc[i][j][c] = 0.f;

    issue(0, 0);
    issue(1, 1);

    const int l16 = lane & 15;
    const int lh  = lane >> 4;       // 0..1

    for (int it = 0; it < KTILES; it++) {
        if (it == KTILES - 1) CP_WAIT0(); else CP_WAIT1();
        __syncthreads();
        if (it + 2 < KTILES) issue(it + 2, (it + 2) % 3);

        const int st = it % 3;
        const uint32_t aBase = sA_u + (uint32_t)(st * A_ST) * 2;
        const uint32_t bBase = sB_u + (uint32_t)(st * B_ST_B);

        #pragma unroll
        for (int kk = 0; kk < 2; kk++) {
            // A fragments: 4 m-tiles of 16x16
            uint32_t am[4][4];
            #pragma unroll
            for (int i = 0; i < 4; i++) {
                int row = wm * 64 + i * 16 + l16;
                ldsm_x4(am[i], aBase + (uint32_t)(row * LDA + kk * 16 + lh * 8) * 2);
            }
            // B fragments: 2 trans-ldsm -> 4 n8-tiles
            uint32_t bf[2][4];
            #pragma unroll
            for (int jj = 0; jj < 2; jj++) {
                int r = kk * 16 + l16;
                int c = wn * 4 + jj * 2 + lh;
                ldsm_x4t(bf[jj], bBase + (uint32_t)(r * 256 + ((c ^ (r & 7)) << 4)));
            }
            #pragma unroll
            for (int i = 0; i < 4; i++) {
                #pragma unroll
                for (int jj = 0; jj < 2; jj++) {
                    mma16816(acc[i][jj * 2 + 0], am[i], bf[jj][0], bf[jj][1]);
                    mma16816(acc[i][jj * 2 + 1], am[i], bf[jj][2], bf[jj][3]);
                }
            }
        }
    }

    // direct register epilogue
    const int row0 = m0 + wm * 64 + (lane >> 2);
    const int gnb  = n0 + wn * 32 + 2 * (lane & 3);
    #pragma unroll
    for (int i = 0; i < 4; i++) {
        #pragma unroll
        for (int j = 0; j < 4; j++) {
            int gn = gnb + j * 8;
            epi(row0 + i * 16,     gn, acc[i][j][0], acc[i][j][1]);
            epi(row0 + i * 16 + 8, gn, acc[i][j][2], acc[i][j][3]);
        }
    }
}

// ===========================================================================
// Kernel 1: QKV GEMM + scatter epilogue (half2 stores into g_Qh/g_Kh/g_Vh)
// ===========================================================================
__global__ void __launch_bounds__(256, 2) gemm_qkv_kernel(const __half* __restrict__ X,
                                                          const __half* __restrict__ W)
{
    const int m0 = blockIdx.y * BM;
    const int n0 = blockIdx.x * BN;
    const bool mtail = (m0 + BM > MROWS);

    gemm_mma(X, W, QKV_N, m0, n0, mtail,
        [&](int gm, int gn, float v0, float v1) {
            if (gm >= MROWS) return;
            int b   = gm / SEQ;
            int tok = gm - b * SEQ;
            int s   = gn / EMBED;
            int rem = gn - s * EMBED;
            int h   = rem >> 6;
            int d   = rem & 63;
            size_t idx = ((size_t)(b * HEADS + h) * SEQ + tok) * HDIM + d;
            if (s == 0) {
                *(__half2*)(g_Qh + idx) = __floats2half2_rn(v0 * ATT_SCALE, v1 * ATT_SCALE);
            } else if (s == 1) {
                *(__half2*)(g_Kh + idx) = __floats2half2_rn(v0, v1);
            } else {
                *(__half2*)(g_Vh + idx) = __floats2half2_rn(v0, v1);
            }
        });
}

// ===========================================================================
// Kernel 3: projection GEMM.  out = g_Oh @ Wp + bias  (fp32 float2 stores)
// ===========================================================================
__global__ void __launch_bounds__(256, 2) gemm_proj_kernel(const __half* __restrict__ A,
                                                           const __half* __restrict__ W,
                                                           const float* __restrict__ bias,
                                                           float* __restrict__ out)
{
    const int m0 = blockIdx.y * BM;
    const int n0 = blockIdx.x * BN;
    const bool mtail = (m0 + BM > MROWS);

    gemm_mma(A, W, EMBED, m0, n0, mtail,
        [&](int gm, int gn, float v0, float v1) {
            if (gm >= MROWS) return;
            float2 v;
            v.x = v0 + bias[gn];
            v.y = v1 + bias[gn + 1];
            *(float2*)(out + (size_t)gm * EMBED + gn) = v;
        });
}

// ===========================================================================
// Kernel 2: flash attention, FA2-style (unchanged from R7)
// ===========================================================================
#define KV_TILES ((SEQ + 63) / 64)                 // 10
#define LDH 72
#define KV_TILE_H (64 * LDH)
#define Q_TILE_H  (128 * LDH)
#define ATTN_SMEM ((Q_TILE_H + 4 * KV_TILE_H) * 2) // 55296 B

__global__ void __launch_bounds__(256) attn_kernel()
{
    extern __shared__ __half smh[];
    __half* Qs = smh;                    // 128 x 72
    __half* Ks = Qs + Q_TILE_H;          // 2 stages x 64 x 72
    __half* Vs = Ks + 2 * KV_TILE_H;     // 2 stages x 64 x 72

    const int tid  = threadIdx.x;
    const int warp = tid >> 5;
    const int lane = tid & 31;
    const int bh   = blockIdx.y;
    const int b    = bh / HEADS;
    const int h    = bh - b * HEADS;
    const int q0   = blockIdx.x * 128;

    const __half* Qg = g_Qh + (size_t)bh * SEQ * HDIM;
    const __half* Kg = g_Kh + (size_t)bh * SEQ * HDIM;
    const __half* Vg = g_Vh + (size_t)bh * SEQ * HDIM;

    uint32_t Qs_u = smem_u32(Qs);
    uint32_t Ks_u = Qs_u + Q_TILE_H * 2;
    uint32_t Vs_u = Ks_u + 2 * KV_TILE_H * 2;

    auto issue_kv = [&](int kt, int st) {
        const int kbase = kt * 64;
        #pragma unroll
        for (int j = 0; j < 2; j++) {
            int i  = tid + j * 256;
            int r  = i >> 3;
            int c8 = (i & 7) << 3;
            int ki = kbase + r;
            bool p = ki < SEQ;
            uint32_t off = (uint32_t)(st * KV_TILE_H + r * LDH + c8) * 2;
            cp16(Ks_u + off, Kg + (size_t)ki * HDIM + c8, p);
            cp16(Vs_u + off, Vg + (size_t)ki * HDIM + c8, p);
        }
        CP_COMMIT();
    };

    #pragma unroll
    for (int j = 0; j < 4; j++) {
        int i  = tid + j * 256;
        int r  = i >> 3;
        int c8 = (i & 7) << 3;
        int qi = q0 + r;
        cp16(Qs_u + (uint32_t)(r * LDH + c8) * 2, Qg + (size_t)qi * HDIM + c8, qi < SEQ);
    }
    issue_kv(0, 0);

    CP_WAIT0();
    __syncthreads();

    uint32_t qa[4][4];
    {
        const int l8  = lane & 7;
        const int sel = lane >> 3;
        #pragma unroll
        for (int kk = 0; kk < 4; kk++) {
            uint32_t addr = Qs_u +
                (uint32_t)((warp * 16 + (sel & 1) * 8 + l8) * LDH + kk * 16 + (sel >> 1) * 8) * 2;
            ldsm_x4(qa[kk], addr);
        }
    }
    if (KV_TILES > 1) issue_kv(1, 1);

    float o[8][4];
    #pragma unroll
    for (int j = 0; j < 8; j++)
        #pragma unroll
        for (int c = 0; c < 4; c++) o[j][c] = 0.f;
    float mrow[2] = {-1e30f, -1e30f};
    float lrow[2] = {0.f, 0.f};

    const int l16 = lane & 15;

    for (int kt = 0; kt < KV_TILES; kt++) {
        const int st = kt & 1;
        if (kt > 0) {
            CP_WAIT0();
            __syncthreads();
            if (kt + 1 < KV_TILES) issue_kv(kt + 1, st ^ 1);
        }
        const uint32_t Kt_u = Ks_u + (uint32_t)(st * KV_TILE_H) * 2;
        const uint32_t Vt_u = Vs_u + (uint32_t)(st * KV_TILE_H) * 2;

        float s[8][4];
        #pragma unroll
        for (int j = 0; j < 8; j++)
            #pragma unroll
            for (int c = 0; c < 4; c++) s[j][c] = 0.f;

        #pragma unroll
        for (int kk = 0; kk < 4; kk++) {
            #pragma unroll
            for (int j = 0; j < 8; j++) {
                uint32_t b0, b1;
                uint32_t addr = Kt_u +
                    (uint32_t)((j * 8 + (l16 & 7)) * LDH + kk * 16 + (l16 >> 3) * 8) * 2;
                ldsm_x2(b0, b1, addr);
                mma16816(s[j], qa[kk], b0, b1);
            }
        }

        const int kvbase = kt * 64;
        const int kvc = kvbase + 2 * (lane & 3);
        float mx0 = mrow[0], mx1 = mrow[1];
        #pragma unroll
        for (int j = 0; j < 8; j++) {
            int kv = kvc + j * 8;
            if (kv     >= SEQ) { s[j][0] = -1e30f; s[j][2] = -1e30f; }
            if (kv + 1 >= SEQ) { s[j][1] = -1e30f; s[j][3] = -1e30f; }
            mx0 = fmaxf(mx0, fmaxf(s[j][0], s[j][1]));
            mx1 = fmaxf(mx1, fmaxf(s[j][2], s[j][3]));
        }
        mx0 = fmaxf(mx0, __shfl_xor_sync(0xffffffffu, mx0, 1));
        mx0 = fmaxf(mx0, __shfl_xor_sync(0xffffffffu, mx0, 2));
        mx1 = fmaxf(mx1, __shfl_xor_sync(0xffffffffu, mx1, 1));
        mx1 = fmaxf(mx1, __shfl_xor_sync(0xffffffffu, mx1, 2));

        const float alpha0 = __expf(mrow[0] - mx0);
        const float alpha1 = __expf(mrow[1] - mx1);
        mrow[0] = mx0; mrow[1] = mx1;

        float ls0 = 0.f, ls1 = 0.f;
        uint32_t pa[4][4];
        #pragma unroll
        for (int j = 0; j < 8; j++) {
            float p0 = __expf(s[j][0] - mx0);
            float p1 = __expf(s[j][1] - mx0);
            float p2 = __expf(s[j][2] - mx1);
            float p3 = __expf(s[j][3] - mx1);
            ls0 += p0 + p1;
            ls1 += p2 + p3;
            __half2 h01 = __floats2half2_rn(p0, p1);
            __half2 h23 = __floats2half2_rn(p2, p3);
            pa[j >> 1][(j & 1) * 2 + 0] = *(uint32_t*)&h01;
            pa[j >> 1][(j & 1) * 2 + 1] = *(uint32_t*)&h23;
        }
        ls0 += __shfl_xor_sync(0xffffffffu, ls0, 1);
        ls0 += __shfl_xor_sync(0xffffffffu, ls0, 2);
        ls1 += __shfl_xor_sync(0xffffffffu, ls1, 1);
        ls1 += __shfl_xor_sync(0xffffffffu, ls1, 2);
        lrow[0] = lrow[0] * alpha0 + ls0;
        lrow[1] = lrow[1] * alpha1 + ls1;

        #pragma unroll
        for (int j = 0; j < 8; j++) {
            o[j][0] *= alpha0; o[j][1] *= alpha0;
            o[j][2] *= alpha1; o[j][3] *= alpha1;
        }

        #pragma unroll
        for (int kk = 0; kk < 4; kk++) {
            #pragma unroll
            for (int j = 0; j < 8; j++) {
                uint32_t b0, b1;
                uint32_t addr = Vt_u + (uint32_t)((kk * 16 + l16) * LDH + j * 8) * 2;
                ldsm_x2t(b0, b1, addr);
                mma16816(o[j], pa[kk], b0, b1);
            }
        }
    }

    const float rinv0 = 1.0f / lrow[0];
    const float rinv1 = 1.0f / lrow[1];
    const int qi0 = q0 + warp * 16 + (lane >> 2);
    const int qi1 = qi0 + 8;
    const int dbase = h * HDIM + 2 * (lane & 3);
    #pragma unroll
    for (int j = 0; j < 8; j++) {
        int d = dbase + j * 8;
        if (qi0 < SEQ) {
            __half2 v = __floats2half2_rn(o[j][0] * rinv0, o[j][1] * rinv0);
            *(__half2*)(g_Oh + (size_t)(b * SEQ + qi0) * EMBED + d) = v;
        }
        if (qi1 < SEQ) {
            __half2 v = __floats2half2_rn(o[j][2] * rinv1, o[j][3] * rinv1);
            *(__half2*)(g_Oh + (size_t)(b * SEQ + qi1) * EMBED + d) = v;
        }
    }
}

// ===========================================================================
// Aux: fp32 -> fp16 conversion (vectorized, grid-stride)
// ===========================================================================
__global__ void f2h_kernel(const float* __restrict__ src, __half* __restrict__ dst,
                           size_t n8)
{
    for (size_t i = blockIdx.x * blockDim.x + threadIdx.x; i < n8;
         i += (size_t)gridDim.x * blockDim.x) {
        float4 a = ((const float4*)src)[2 * i];
        float4 b = ((const float4*)src)[2 * i + 1];
        __half2 h0 = __floats2half2_rn(a.x, a.y);
        __half2 h1 = __floats2half2_rn(a.z, a.w);
        __half2 h2 = __floats2half2_rn(b.x, b.y);
        __half2 h3 = __floats2half2_rn(b.z, b.w);
        uint4 o;
        o.x = *(uint32_t*)&h0; o.y = *(uint32_t*)&h1;
        o.z = *(uint32_t*)&h2; o.w = *(uint32_t*)&h3;
        ((uint4*)dst)[i] = o;
    }
}

// ===========================================================================
extern "C" void kernel_launch(void* const* d_in, const int* in_sizes, int n_in,
                              void* d_out, int out_size)
{
    (void)in_sizes; (void)n_in; (void)out_size;
    const float* x      = (const float*)d_in[0];
    const float* w_qkv  = (const float*)d_in[1];
    const float* w_proj = (const float*)d_in[2];
    const float* b_proj = (const float*)d_in[3];
    float* out = (float*)d_out;

    cudaFuncSetAttribute(gemm_qkv_kernel,  cudaFuncAttributeMaxDynamicSharedMemorySize, GEMM_SMEM_BYTES);
    cudaFuncSetAttribute(gemm_proj_kernel, cudaFuncAttributeMaxDynamicSharedMemorySize, GEMM_SMEM_BYTES);
    cudaFuncSetAttribute(attn_kernel,      cudaFuncAttributeMaxDynamicSharedMemorySize, (int)ATTN_SMEM);

    __half *dXh, *dWqkvh, *dWprojh, *dOh;
    cudaGetSymbolAddress((void**)&dXh,     g_Xh);
    cudaGetSymbolAddress((void**)&dWqkvh,  g_Wqkvh);
    cudaGetSymbolAddress((void**)&dWprojh, g_Wprojh);
    cudaGetSymbolAddress((void**)&dOh,     g_Oh);

    f2h_kernel<<<1184, 256>>>(x,      dXh,     (size_t)MROWS * EMBED / 8);
    f2h_kernel<<<592,  256>>>(w_qkv,  dWqkvh,  (size_t)EMBED * QKV_N / 8);
    f2h_kernel<<<296,  256>>>(w_proj, dWprojh, (size_t)EMBED * EMBED / 8);

    const int mblocks = (MROWS + BM - 1) / BM;   // 145
    gemm_qkv_kernel<<<dim3(QKV_N / BN, mblocks), 256, GEMM_SMEM_BYTES>>>(dXh, dWqkvh);

    const int qblocks = (SEQ + 127) / 128;       // 5
    attn_kernel<<<dim3(qblocks, BATCH * HEADS), 256, ATTN_SMEM>>>();

    gemm_proj_kernel<<<dim3(EMBED / BN, mblocks), 256, GEMM_SMEM_BYTES>>>(dOh, dWprojh, b_proj, out);
}

// round 9
// speedup vs baseline: 5.9598x; 1.0430x over previous
#include <cuda_runtime.h>
#include <cuda_fp16.h>
#include <cstdint>

#define BATCH   32
#define SEQ     577
#define EMBED   768
#define HEADS   12
#define HDIM    64
#define MROWS   (BATCH * SEQ)        // 18464
#define QKV_N   (3 * EMBED)          // 2304
#define ATT_SCALE 0.125f             // HDIM^-0.5

// ---------------- scratch (module-load allocated, no runtime allocs) -------
__device__ __half g_Qh[(size_t)BATCH * HEADS * SEQ * HDIM];   // [b,h,n,d], pre-scaled
__device__ __half g_Kh[(size_t)BATCH * HEADS * SEQ * HDIM];
__device__ __half g_Vh[(size_t)BATCH * HEADS * SEQ * HDIM];
__device__ __half g_Oh[(size_t)MROWS * EMBED];                // attention out (half)
__device__ __half g_Xh[(size_t)MROWS * EMBED];                // half X
__device__ __half g_Wqkvh[(size_t)EMBED * QKV_N];             // half W_qkv (row-major)
__device__ __half g_Wprojh[(size_t)EMBED * EMBED];            // half W_proj (row-major)

// ---------------- PTX helpers ----------------------------------------------
__device__ __forceinline__ uint32_t smem_u32(const void* p) {
    uint32_t a;
    asm("{ .reg .u64 t; cvta.to.shared.u64 t, %1; cvt.u32.u64 %0, t; }"
        : "=r"(a) : "l"(p));
    return a;
}
__device__ __forceinline__ void cp16(uint32_t dst, const void* src, bool pred) {
    int sz = pred ? 16 : 0;
    asm volatile("cp.async.cg.shared.global [%0], [%1], 16, %2;\n"
                 :: "r"(dst), "l"(src), "r"(sz));
}
#define CP_COMMIT() asm volatile("cp.async.commit_group;\n" ::: "memory")
#define CP_WAIT0()  asm volatile("cp.async.wait_group 0;\n" ::: "memory")

__device__ __forceinline__ void ldsm_x4(uint32_t (&r)[4], uint32_t addr) {
    asm volatile("ldmatrix.sync.aligned.m8n8.x4.shared.b16 {%0,%1,%2,%3}, [%4];"
                 : "=r"(r[0]), "=r"(r[1]), "=r"(r[2]), "=r"(r[3]) : "r"(addr));
}
__device__ __forceinline__ void ldsm_x4t(uint32_t (&r)[4], uint32_t addr) {
    asm volatile("ldmatrix.sync.aligned.m8n8.x4.trans.shared.b16 {%0,%1,%2,%3}, [%4];"
                 : "=r"(r[0]), "=r"(r[1]), "=r"(r[2]), "=r"(r[3]) : "r"(addr));
}
__device__ __forceinline__ void ldsm_x2(uint32_t& r0, uint32_t& r1, uint32_t addr) {
    asm volatile("ldmatrix.sync.aligned.m8n8.x2.shared.b16 {%0,%1}, [%2];"
                 : "=r"(r0), "=r"(r1) : "r"(addr));
}
__device__ __forceinline__ void ldsm_x2t(uint32_t& r0, uint32_t& r1, uint32_t addr) {
    asm volatile("ldmatrix.sync.aligned.m8n8.x2.trans.shared.b16 {%0,%1}, [%2];"
                 : "=r"(r0), "=r"(r1) : "r"(addr));
}
__device__ __forceinline__ void mma16816(float (&d)[4], const uint32_t (&a)[4],
                                         uint32_t b0, uint32_t b1) {
    asm volatile("mma.sync.aligned.m16n8k16.row.col.f32.f16.f16.f32 "
                 "{%0,%1,%2,%3}, {%4,%5,%6,%7}, {%8,%9}, {%0,%1,%2,%3};"
                 : "+f"(d[0]), "+f"(d[1]), "+f"(d[2]), "+f"(d[3])
                 : "r"(a[0]), "r"(a[1]), "r"(a[2]), "r"(a[3]), "r"(b0), "r"(b1));
}

// ---------------- GEMM tiling (raw mma, fp16) -------------------------------
// BM=128, BN=128, BK=64; 256 threads = 8 warps as 2(m) x 4(n); warp tile 64x32.
// 2-stage double buffer: issue(it+1) right after barrier, overlap with 4 k-steps.
// A: padded rows (72 halves, 36-bank stride) — conflict-free ldsm.
// B: 64 rows x 16 chunks(16B), chunk swizzle c^(r&7) — conflict-free trans ldsm.
// Epilogue: direct register->global stores.
#define BM 128
#define BN 128
#define BK 64
#define LDA 72
#define A_ST (BM * LDA)              // halves per A stage (9216)
#define B_ST_B 16384                 // bytes per B stage
#define KTILES (EMBED / BK)          // 12
#define GEMM_SMEM_BYTES (2 * (A_ST * 2 + B_ST_B))   // 69632

template <typename EPI>
__device__ __forceinline__ void gemm_mma(
    const __half* __restrict__ Ag, const __half* __restrict__ Bg, int ldb_g,
    int m0, int n0, bool mtail, EPI epi)
{
    extern __shared__ __half smh[];
    uint32_t sA_u = smem_u32(smh);
    uint32_t sB_u = sA_u + 2 * A_ST * 2;

    const int tid  = threadIdx.x;
    const int warp = tid >> 5;
    const int lane = tid & 31;
    const int wm   = warp >> 2;      // 0..1
    const int wn   = warp & 3;       // 0..3

    auto issue = [&](int kt, int st) {
        const int k0 = kt * BK;
        // A: 128 rows x 8 chunks -> 4/thread
        #pragma unroll
        for (int j = 0; j < 4; j++) {
            int i  = tid + j * 256;
            int r  = i >> 3;
            int ch = i & 7;
            int gm = m0 + r;
            bool p = !mtail || (gm < MROWS);
            cp16(sA_u + (uint32_t)(st * A_ST + r * LDA + ch * 8) * 2,
                 Ag + (size_t)gm * EMBED + k0 + ch * 8, p);
        }
        // B: 64 rows x 16 chunks -> 4/thread, swizzled
        #pragma unroll
        for (int j = 0; j < 4; j++) {
            int i  = tid + j * 256;
            int r  = i >> 4;
            int c  = i & 15;
            cp16(sB_u + (uint32_t)(st * B_ST_B + r * 256 + ((c ^ (r & 7)) << 4)),
                 Bg + (size_t)(k0 + r) * ldb_g + n0 + c * 8, true);
        }
        CP_COMMIT();
    };

    float acc[4][4][4];
    #pragma unroll
    for (int i = 0; i < 4; i++)
        #pragma unroll
        for (int j = 0; j < 4; j++)
            #pragma unroll
            for (int c = 0; c < 4; c++) acc[i][j][c] = 0.f;

    issue(0, 0);

    const int l16 = lane & 15;
    const int lh  = lane >> 4;       // 0..1

    for (int it = 0; it < KTILES; it++) {
        CP_WAIT0();
        __syncthreads();
        if (it + 1 < KTILES) issue(it + 1, (it + 1) & 1);

        const int st = it & 1;
        const uint32_t aBase = sA_u + (uint32_t)(st * A_ST) * 2;
        const uint32_t bBase = sB_u + (uint32_t)(st * B_ST_B);

        #pragma unroll
        for (int kk = 0; kk < 4; kk++) {
            uint32_t am[4][4];
            #pragma unroll
            for (int i = 0; i < 4; i++) {
                int row = wm * 64 + i * 16 + l16;
                ldsm_x4(am[i], aBase + (uint32_t)(row * LDA + kk * 16 + lh * 8) * 2);
            }
            uint32_t bf[2][4];
            #pragma unroll
            for (int jj = 0; jj < 2; jj++) {
                int r = kk * 16 + l16;
                int c = wn * 4 + jj * 2 + lh;
                ldsm_x4t(bf[jj], bBase + (uint32_t)(r * 256 + ((c ^ (r & 7)) << 4)));
            }
            #pragma unroll
            for (int i = 0; i < 4; i++) {
                #pragma unroll
                for (int jj = 0; jj < 2; jj++) {
                    mma16816(acc[i][jj * 2 + 0], am[i], bf[jj][0], bf[jj][1]);
                    mma16816(acc[i][jj * 2 + 1], am[i], bf[jj][2], bf[jj][3]);
                }
            }
        }
        __syncthreads();   // all warps done with stage st before next issue overwrites
    }

    // direct register epilogue
    const int row0 = m0 + wm * 64 + (lane >> 2);
    const int gnb  = n0 + wn * 32 + 2 * (lane & 3);
    #pragma unroll
    for (int i = 0; i < 4; i++) {
        #pragma unroll
        for (int j = 0; j < 4; j++) {
            int gn = gnb + j * 8;
            epi(row0 + i * 16,     gn, acc[i][j][0], acc[i][j][1]);
            epi(row0 + i * 16 + 8, gn, acc[i][j][2], acc[i][j][3]);
        }
    }
}

// ===========================================================================
// Kernel 1: QKV GEMM + scatter epilogue (half2 stores into g_Qh/g_Kh/g_Vh)
// ===========================================================================
__global__ void __launch_bounds__(256, 2) gemm_qkv_kernel(const __half* __restrict__ X,
                                                          const __half* __restrict__ W)
{
    const int m0 = blockIdx.y * BM;
    const int n0 = blockIdx.x * BN;
    const bool mtail = (m0 + BM > MROWS);

    gemm_mma(X, W, QKV_N, m0, n0, mtail,
        [&](int gm, int gn, float v0, float v1) {
            if (gm >= MROWS) return;
            int b   = gm / SEQ;
            int tok = gm - b * SEQ;
            int s   = gn / EMBED;
            int rem = gn - s * EMBED;
            int h   = rem >> 6;
            int d   = rem & 63;
            size_t idx = ((size_t)(b * HEADS + h) * SEQ + tok) * HDIM + d;
            if (s == 0) {
                *(__half2*)(g_Qh + idx) = __floats2half2_rn(v0 * ATT_SCALE, v1 * ATT_SCALE);
            } else if (s == 1) {
                *(__half2*)(g_Kh + idx) = __floats2half2_rn(v0, v1);
            } else {
                *(__half2*)(g_Vh + idx) = __floats2half2_rn(v0, v1);
            }
        });
}

// ===========================================================================
// Kernel 3: projection GEMM.  out = g_Oh @ Wp + bias  (fp32 float2 stores)
// ===========================================================================
__global__ void __launch_bounds__(256, 2) gemm_proj_kernel(const __half* __restrict__ A,
                                                           const __half* __restrict__ W,
                                                           const float* __restrict__ bias,
                                                           float* __restrict__ out)
{
    const int m0 = blockIdx.y * BM;
    const int n0 = blockIdx.x * BN;
    const bool mtail = (m0 + BM > MROWS);

    gemm_mma(A, W, EMBED, m0, n0, mtail,
        [&](int gm, int gn, float v0, float v1) {
            if (gm >= MROWS) return;
            float2 v;
            v.x = v0 + bias[gn];
            v.y = v1 + bias[gn + 1];
            *(float2*)(out + (size_t)gm * EMBED + gn) = v;
        });
}

// ===========================================================================
// Kernel 2: flash attention, FA2-style (unchanged from R8)
// ===========================================================================
#define KV_TILES ((SEQ + 63) / 64)                 // 10
#define LDH 72
#define KV_TILE_H (64 * LDH)
#define Q_TILE_H  (128 * LDH)
#define ATTN_SMEM ((Q_TILE_H + 4 * KV_TILE_H) * 2) // 55296 B

__global__ void __launch_bounds__(256) attn_kernel()
{
    extern __shared__ __half smh[];
    const int tid  = threadIdx.x;
    const int warp = tid >> 5;
    const int lane = tid & 31;
    const int bh   = blockIdx.y;
    const int b    = bh / HEADS;
    const int h    = bh - b * HEADS;
    const int q0   = blockIdx.x * 128;

    const __half* Qg = g_Qh + (size_t)bh * SEQ * HDIM;
    const __half* Kg = g_Kh + (size_t)bh * SEQ * HDIM;
    const __half* Vg = g_Vh + (size_t)bh * SEQ * HDIM;

    uint32_t Qs_u = smem_u32(smh);
    uint32_t Ks_u = Qs_u + Q_TILE_H * 2;
    uint32_t Vs_u = Ks_u + 2 * KV_TILE_H * 2;

    auto issue_kv = [&](int kt, int st) {
        const int kbase = kt * 64;
        #pragma unroll
        for (int j = 0; j < 2; j++) {
            int i  = tid + j * 256;
            int r  = i >> 3;
            int c8 = (i & 7) << 3;
            int ki = kbase + r;
            bool p = ki < SEQ;
            uint32_t off = (uint32_t)(st * KV_TILE_H + r * LDH + c8) * 2;
            cp16(Ks_u + off, Kg + (size_t)ki * HDIM + c8, p);
            cp16(Vs_u + off, Vg + (size_t)ki * HDIM + c8, p);
        }
        CP_COMMIT();
    };

    #pragma unroll
    for (int j = 0; j < 4; j++) {
        int i  = tid + j * 256;
        int r  = i >> 3;
        int c8 = (i & 7) << 3;
        int qi = q0 + r;
        cp16(Qs_u + (uint32_t)(r * LDH + c8) * 2, Qg + (size_t)qi * HDIM + c8, qi < SEQ);
    }
    issue_kv(0, 0);

    CP_WAIT0();
    __syncthreads();

    uint32_t qa[4][4];
    {
        const int l8  = lane & 7;
        const int sel = lane >> 3;
        #pragma unroll
        for (int kk = 0; kk < 4; kk++) {
            uint32_t addr = Qs_u +
                (uint32_t)((warp * 16 + (sel & 1) * 8 + l8) * LDH + kk * 16 + (sel >> 1) * 8) * 2;
            ldsm_x4(qa[kk], addr);
        }
    }
    if (KV_TILES > 1) issue_kv(1, 1);

    float o[8][4];
    #pragma unroll
    for (int j = 0; j < 8; j++)
        #pragma unroll
        for (int c = 0; c < 4; c++) o[j][c] = 0.f;
    float mrow[2] = {-1e30f, -1e30f};
    float lrow[2] = {0.f, 0.f};

    const int l16 = lane & 15;

    for (int kt = 0; kt < KV_TILES; kt++) {
        const int st = kt & 1;
        if (kt > 0) {
            CP_WAIT0();
            __syncthreads();
            if (kt + 1 < KV_TILES) issue_kv(kt + 1, st ^ 1);
        }
        const uint32_t Kt_u = Ks_u + (uint32_t)(st * KV_TILE_H) * 2;
        const uint32_t Vt_u = Vs_u + (uint32_t)(st * KV_TILE_H) * 2;

        float s[8][4];
        #pragma unroll
        for (int j = 0; j < 8; j++)
            #pragma unroll
            for (int c = 0; c < 4; c++) s[j][c] = 0.f;

        #pragma unroll
        for (int kk = 0; kk < 4; kk++) {
            #pragma unroll
            for (int j = 0; j < 8; j++) {
                uint32_t b0, b1;
                uint32_t addr = Kt_u +
                    (uint32_t)((j * 8 + (l16 & 7)) * LDH + kk * 16 + (l16 >> 3) * 8) * 2;
                ldsm_x2(b0, b1, addr);
                mma16816(s[j], qa[kk], b0, b1);
            }
        }

        const int kvbase = kt * 64;
        const int kvc = kvbase + 2 * (lane & 3);
        float mx0 = mrow[0], mx1 = mrow[1];
        #pragma unroll
        for (int j = 0; j < 8; j++) {
            int kv = kvc + j * 8;
            if (kv     >= SEQ) { s[j][0] = -1e30f; s[j][2] = -1e30f; }
            if (kv + 1 >= SEQ) { s[j][1] = -1e30f; s[j][3] = -1e30f; }
            mx0 = fmaxf(mx0, fmaxf(s[j][0], s[j][1]));
            mx1 = fmaxf(mx1, fmaxf(s[j][2], s[j][3]));
        }
        mx0 = fmaxf(mx0, __shfl_xor_sync(0xffffffffu, mx0, 1));
        mx0 = fmaxf(mx0, __shfl_xor_sync(0xffffffffu, mx0, 2));
        mx1 = fmaxf(mx1, __shfl_xor_sync(0xffffffffu, mx1, 1));
        mx1 = fmaxf(mx1, __shfl_xor_sync(0xffffffffu, mx1, 2));

        const float alpha0 = __expf(mrow[0] - mx0);
        const float alpha1 = __expf(mrow[1] - mx1);
        mrow[0] = mx0; mrow[1] = mx1;

        float ls0 = 0.f, ls1 = 0.f;
        uint32_t pa[4][4];
        #pragma unroll
        for (int j = 0; j < 8; j++) {
            float p0 = __expf(s[j][0] - mx0);
            float p1 = __expf(s[j][1] - mx0);
            float p2 = __expf(s[j][2] - mx1);
            float p3 = __expf(s[j][3] - mx1);
            ls0 += p0 + p1;
            ls1 += p2 + p3;
            __half2 h01 = __floats2half2_rn(p0, p1);
            __half2 h23 = __floats2half2_rn(p2, p3);
            pa[j >> 1][(j & 1) * 2 + 0] = *(uint32_t*)&h01;
            pa[j >> 1][(j & 1) * 2 + 1] = *(uint32_t*)&h23;
        }
        ls0 += __shfl_xor_sync(0xffffffffu, ls0, 1);
        ls0 += __shfl_xor_sync(0xffffffffu, ls0, 2);
        ls1 += __shfl_xor_sync(0xffffffffu, ls1, 1);
        ls1 += __shfl_xor_sync(0xffffffffu, ls1, 2);
        lrow[0] = lrow[0] * alpha0 + ls0;
        lrow[1] = lrow[1] * alpha1 + ls1;

        #pragma unroll
        for (int j = 0; j < 8; j++) {
            o[j][0] *= alpha0; o[j][1] *= alpha0;
            o[j][2] *= alpha1; o[j][3] *= alpha1;
        }

        #pragma unroll
        for (int kk = 0; kk < 4; kk++) {
            #pragma unroll
            for (int j = 0; j < 8; j++) {
                uint32_t b0, b1;
                uint32_t addr = Vt_u + (uint32_t)((kk * 16 + l16) * LDH + j * 8) * 2;
                ldsm_x2t(b0, b1, addr);
                mma16816(o[j], pa[kk], b0, b1);
            }
        }
    }

    const float rinv0 = 1.0f / lrow[0];
    const float rinv1 = 1.0f / lrow[1];
    const int qi0 = q0 + warp * 16 + (lane >> 2);
    const int qi1 = qi0 + 8;
    const int dbase = h * HDIM + 2 * (lane & 3);
    #pragma unroll
    for (int j = 0; j < 8; j++) {
        int d = dbase + j * 8;
        if (qi0 < SEQ) {
            __half2 v = __floats2half2_rn(o[j][0] * rinv0, o[j][1] * rinv0);
            *(__half2*)(g_Oh + (size_t)(b * SEQ + qi0) * EMBED + d) = v;
        }
        if (qi1 < SEQ) {
            __half2 v = __floats2half2_rn(o[j][2] * rinv1, o[j][3] * rinv1);
            *(__half2*)(g_Oh + (size_t)(b * SEQ + qi1) * EMBED + d) = v;
        }
    }
}

// ===========================================================================
// Aux: single fused fp32 -> fp16 conversion over X, Wqkv, Wproj
// ===========================================================================
#define N8_X  ((size_t)MROWS * EMBED / 8)
#define N8_W1 ((size_t)EMBED * QKV_N / 8)
#define N8_W2 ((size_t)EMBED * EMBED / 8)

__global__ void f2h_all_kernel(const float* __restrict__ x,
                               const float* __restrict__ w1,
                               const float* __restrict__ w2)
{
    const size_t ntot = N8_X + N8_W1 + N8_W2;
    for (size_t i = blockIdx.x * blockDim.x + threadIdx.x; i < ntot;
         i += (size_t)gridDim.x * blockDim.x) {
        const float* src;
        __half* dst;
        size_t k;
        if (i < N8_X)             { src = x;  dst = g_Xh;     k = i; }
        else if (i < N8_X + N8_W1){ src = w1; dst = g_Wqkvh;  k = i - N8_X; }
        else                      { src = w2; dst = g_Wprojh; k = i - N8_X - N8_W1; }
        float4 a = ((const float4*)src)[2 * k];
        float4 b = ((const float4*)src)[2 * k + 1];
        __half2 h0 = __floats2half2_rn(a.x, a.y);
        __half2 h1 = __floats2half2_rn(a.z, a.w);
        __half2 h2 = __floats2half2_rn(b.x, b.y);
        __half2 h3 = __floats2half2_rn(b.z, b.w);
        uint4 o;
        o.x = *(uint32_t*)&h0; o.y = *(uint32_t*)&h1;
        o.z = *(uint32_t*)&h2; o.w = *(uint32_t*)&h3;
        ((uint4*)dst)[k] = o;
    }
}

// ===========================================================================
extern "C" void kernel_launch(void* const* d_in, const int* in_sizes, int n_in,
                              void* d_out, int out_size)
{
    (void)in_sizes; (void)n_in; (void)out_size;
    const float* x      = (const float*)d_in[0];
    const float* w_qkv  = (const float*)d_in[1];
    const float* w_proj = (const float*)d_in[2];
    const float* b_proj = (const float*)d_in[3];
    float* out = (float*)d_out;

    cudaFuncSetAttribute(gemm_qkv_kernel,  cudaFuncAttributeMaxDynamicSharedMemorySize, GEMM_SMEM_BYTES);
    cudaFuncSetAttribute(gemm_proj_kernel, cudaFuncAttributeMaxDynamicSharedMemorySize, GEMM_SMEM_BYTES);
    cudaFuncSetAttribute(attn_kernel,      cudaFuncAttributeMaxDynamicSharedMemorySize, (int)ATTN_SMEM);

    __half *dXh, *dWqkvh, *dWprojh, *dOh;
    cudaGetSymbolAddress((void**)&dXh,     g_Xh);
    cudaGetSymbolAddress((void**)&dWqkvh,  g_Wqkvh);
    cudaGetSymbolAddress((void**)&dWprojh, g_Wprojh);
    cudaGetSymbolAddress((void**)&dOh,     g_Oh);

    f2h_all_kernel<<<2048, 256>>>(x, w_qkv, w_proj);

    const int mblocks = (MROWS + BM - 1) / BM;   // 145
    gemm_qkv_kernel<<<dim3(QKV_N / BN, mblocks), 256, GEMM_SMEM_BYTES>>>(dXh, dWqkvh);

    const int qblocks = (SEQ + 127) / 128;       // 5
    attn_kernel<<<dim3(qblocks, BATCH * HEADS), 256, ATTN_SMEM>>>();

    gemm_proj_kernel<<<dim3(EMBED / BN, mblocks), 256, GEMM_SMEM_BYTES>>>(dOh, dWprojh, b_proj, out);
}

// round 10
// speedup vs baseline: 5.9859x; 1.0044x over previous
#include <cuda_runtime.h>
#include <cuda_fp16.h>
#include <cstdint>

#define BATCH   32
#define SEQ     577
#define EMBED   768
#define HEADS   12
#define HDIM    64
#define MROWS   (BATCH * SEQ)        // 18464
#define QKV_N   (3 * EMBED)          // 2304
#define ATT_SCALE 0.125f             // HDIM^-0.5

// ---------------- scratch (module-load allocated, no runtime allocs) -------
__device__ __half g_Qh[(size_t)BATCH * HEADS * SEQ * HDIM];   // [b,h,n,d], pre-scaled
__device__ __half g_Kh[(size_t)BATCH * HEADS * SEQ * HDIM];
__device__ __half g_Vh[(size_t)BATCH * HEADS * SEQ * HDIM];
__device__ __half g_Oh[(size_t)MROWS * EMBED];                // attention out (half)
__device__ __half g_Xh[(size_t)MROWS * EMBED];                // half X
__device__ __half g_Wqkvh[(size_t)EMBED * QKV_N];             // half W_qkv (row-major)
__device__ __half g_Wprojh[(size_t)EMBED * EMBED];            // half W_proj (row-major)

// ---------------- PTX helpers ----------------------------------------------
__device__ __forceinline__ uint32_t smem_u32(const void* p) {
    uint32_t a;
    asm("{ .reg .u64 t; cvta.to.shared.u64 t, %1; cvt.u32.u64 %0, t; }"
        : "=r"(a) : "l"(p));
    return a;
}
__device__ __forceinline__ void cp16(uint32_t dst, const void* src, bool pred) {
    int sz = pred ? 16 : 0;
    asm volatile("cp.async.cg.shared.global [%0], [%1], 16, %2;\n"
                 :: "r"(dst), "l"(src), "r"(sz));
}
#define CP_COMMIT() asm volatile("cp.async.commit_group;\n" ::: "memory")
#define CP_WAIT1()  asm volatile("cp.async.wait_group 1;\n" ::: "memory")
#define CP_WAIT0()  asm volatile("cp.async.wait_group 0;\n" ::: "memory")

__device__ __forceinline__ void ldsm_x4(uint32_t (&r)[4], uint32_t addr) {
    asm volatile("ldmatrix.sync.aligned.m8n8.x4.shared.b16 {%0,%1,%2,%3}, [%4];"
                 : "=r"(r[0]), "=r"(r[1]), "=r"(r[2]), "=r"(r[3]) : "r"(addr));
}
__device__ __forceinline__ void ldsm_x4t(uint32_t (&r)[4], uint32_t addr) {
    asm volatile("ldmatrix.sync.aligned.m8n8.x4.trans.shared.b16 {%0,%1,%2,%3}, [%4];"
                 : "=r"(r[0]), "=r"(r[1]), "=r"(r[2]), "=r"(r[3]) : "r"(addr));
}
__device__ __forceinline__ void ldsm_x2(uint32_t& r0, uint32_t& r1, uint32_t addr) {
    asm volatile("ldmatrix.sync.aligned.m8n8.x2.shared.b16 {%0,%1}, [%2];"
                 : "=r"(r0), "=r"(r1) : "r"(addr));
}
__device__ __forceinline__ void ldsm_x2t(uint32_t& r0, uint32_t& r1, uint32_t addr) {
    asm volatile("ldmatrix.sync.aligned.m8n8.x2.trans.shared.b16 {%0,%1}, [%2];"
                 : "=r"(r0), "=r"(r1) : "r"(addr));
}
__device__ __forceinline__ void mma16816(float (&d)[4], const uint32_t (&a)[4],
                                         uint32_t b0, uint32_t b1) {
    asm volatile("mma.sync.aligned.m16n8k16.row.col.f32.f16.f16.f32 "
                 "{%0,%1,%2,%3}, {%4,%5,%6,%7}, {%8,%9}, {%0,%1,%2,%3};"
                 : "+f"(d[0]), "+f"(d[1]), "+f"(d[2]), "+f"(d[3])
                 : "r"(a[0]), "r"(a[1]), "r"(a[2]), "r"(a[3]), "r"(b0), "r"(b1));
}

// ---------------- GEMM tiling (raw mma, fp16) -------------------------------
// BM=128, BN=128, BK=64; 256 threads = 8 warps as 2(m) x 4(n); warp tile 64x32.
// 3-stage pipeline, wait_group 1 + ONE __syncthreads per K-iteration.
// A: padded rows (72 halves, 36-bank stride) — conflict-free ldsm.
// B: 64 rows x 16 chunks(16B), chunk swizzle c^(r&7) — conflict-free trans ldsm.
// Epilogue: direct register->global stores.
#define BM 128
#define BN 128
#define BK 64
#define LDA 72
#define A_ST (BM * LDA)              // halves per A stage (9216)
#define B_ST_B 16384                 // bytes per B stage
#define KTILES (EMBED / BK)          // 12
#define GEMM_SMEM_BYTES (3 * (A_ST * 2 + B_ST_B))   // 104448; 2 CTAs = 208.9KB <= 228KB

template <typename EPI>
__device__ __forceinline__ void gemm_mma(
    const __half* __restrict__ Ag, const __half* __restrict__ Bg, int ldb_g,
    int m0, int n0, bool mtail, EPI epi)
{
    extern __shared__ __half smh[];
    uint32_t sA_u = smem_u32(smh);
    uint32_t sB_u = sA_u + 3 * A_ST * 2;

    const int tid  = threadIdx.x;
    const int warp = tid >> 5;
    const int lane = tid & 31;
    const int wm   = warp >> 2;      // 0..1
    const int wn   = warp & 3;       // 0..3

    auto issue = [&](int kt, int st) {
        const int k0 = kt * BK;
        // A: 128 rows x 8 chunks -> 4/thread
        #pragma unroll
        for (int j = 0; j < 4; j++) {
            int i  = tid + j * 256;
            int r  = i >> 3;
            int ch = i & 7;
            int gm = m0 + r;
            bool p = !mtail || (gm < MROWS);
            cp16(sA_u + (uint32_t)(st * A_ST + r * LDA + ch * 8) * 2,
                 Ag + (size_t)gm * EMBED + k0 + ch * 8, p);
        }
        // B: 64 rows x 16 chunks -> 4/thread, swizzled
        #pragma unroll
        for (int j = 0; j < 4; j++) {
            int i  = tid + j * 256;
            int r  = i >> 4;
            int c  = i & 15;
            cp16(sB_u + (uint32_t)(st * B_ST_B + r * 256 + ((c ^ (r & 7)) << 4)),
                 Bg + (size_t)(k0 + r) * ldb_g + n0 + c * 8, true);
        }
        CP_COMMIT();
    };

    float acc[4][4][4];
    #pragma unroll
    for (int i = 0; i < 4; i++)
        #pragma unroll
        for (int j = 0; j < 4; j++)
            #pragma unroll
            for (int c = 0; c < 4; c++) acc[i][j][c] = 0.f;

    issue(0, 0);
    issue(1, 1);

    const int l16 = lane & 15;
    const int lh  = lane >> 4;       // 0..1

    for (int it = 0; it < KTILES; it++) {
        if (it == KTILES - 1) CP_WAIT0(); else CP_WAIT1();
        __syncthreads();             // data(it) visible; compute(it-1) done everywhere
        if (it + 2 < KTILES) issue(it + 2, (it + 2) % 3);

        const int st = it % 3;
        const uint32_t aBase = sA_u + (uint32_t)(st * A_ST) * 2;
        const uint32_t bBase = sB_u + (uint32_t)(st * B_ST_B);

        #pragma unroll
        for (int kk = 0; kk < 4; kk++) {
            uint32_t am[4][4];
            #pragma unroll
            for (int i = 0; i < 4; i++) {
                int row = wm * 64 + i * 16 + l16;
                ldsm_x4(am[i], aBase + (uint32_t)(row * LDA + kk * 16 + lh * 8) * 2);
            }
            uint32_t bf[2][4];
            #pragma unroll
            for (int jj = 0; jj < 2; jj++) {
                int r = kk * 16 + l16;
                int c = wn * 4 + jj * 2 + lh;
                ldsm_x4t(bf[jj], bBase + (uint32_t)(r * 256 + ((c ^ (r & 7)) << 4)));
            }
            #pragma unroll
            for (int i = 0; i < 4; i++) {
                #pragma unroll
                for (int jj = 0; jj < 2; jj++) {
                    mma16816(acc[i][jj * 2 + 0], am[i], bf[jj][0], bf[jj][1]);
                    mma16816(acc[i][jj * 2 + 1], am[i], bf[jj][2], bf[jj][3]);
                }
            }
        }
    }

    // direct register epilogue
    const int row0 = m0 + wm * 64 + (lane >> 2);
    const int gnb  = n0 + wn * 32 + 2 * (lane & 3);
    #pragma unroll
    for (int i = 0; i < 4; i++) {
        #pragma unroll
        for (int j = 0; j < 4; j++) {
            int gn = gnb + j * 8;
            epi(row0 + i * 16,     gn, acc[i][j][0], acc[i][j][1]);
            epi(row0 + i * 16 + 8, gn, acc[i][j][2], acc[i][j][3]);
        }
    }
}

// ===========================================================================
// Kernel 1: QKV GEMM + scatter epilogue (half2 stores into g_Qh/g_Kh/g_Vh)
// ===========================================================================
__global__ void __launch_bounds__(256, 2) gemm_qkv_kernel(const __half* __restrict__ X,
                                                          const __half* __restrict__ W)
{
    const int m0 = blockIdx.y * BM;
    const int n0 = blockIdx.x * BN;
    const bool mtail = (m0 + BM > MROWS);

    gemm_mma(X, W, QKV_N, m0, n0, mtail,
        [&](int gm, int gn, float v0, float v1) {
            if (gm >= MROWS) return;
            int b   = gm / SEQ;
            int tok = gm - b * SEQ;
            int s   = gn / EMBED;
            int rem = gn - s * EMBED;
            int h   = rem >> 6;
            int d   = rem & 63;
            size_t idx = ((size_t)(b * HEADS + h) * SEQ + tok) * HDIM + d;
            if (s == 0) {
                *(__half2*)(g_Qh + idx) = __floats2half2_rn(v0 * ATT_SCALE, v1 * ATT_SCALE);
            } else if (s == 1) {
                *(__half2*)(g_Kh + idx) = __floats2half2_rn(v0, v1);
            } else {
                *(__half2*)(g_Vh + idx) = __floats2half2_rn(v0, v1);
            }
        });
}

// ===========================================================================
// Kernel 3: projection GEMM.  out = g_Oh @ Wp + bias  (fp32 float2 stores)
// ===========================================================================
__global__ void __launch_bounds__(256, 2) gemm_proj_kernel(const __half* __restrict__ A,
                                                           const __half* __restrict__ W,
                                                           const float* __restrict__ bias,
                                                           float* __restrict__ out)
{
    const int m0 = blockIdx.y * BM;
    const int n0 = blockIdx.x * BN;
    const bool mtail = (m0 + BM > MROWS);

    gemm_mma(A, W, EMBED, m0, n0, mtail,
        [&](int gm, int gn, float v0, float v1) {
            if (gm >= MROWS) return;
            float2 v;
            v.x = v0 + bias[gn];
            v.y = v1 + bias[gn + 1];
            *(float2*)(out + (size_t)gm * EMBED + gn) = v;
        });
}

// ===========================================================================
// Kernel 2: flash attention, FA2-style (unchanged from R9)
// ===========================================================================
#define KV_TILES ((SEQ + 63) / 64)                 // 10
#define LDH 72
#define KV_TILE_H (64 * LDH)
#define Q_TILE_H  (128 * LDH)
#define ATTN_SMEM ((Q_TILE_H + 4 * KV_TILE_H) * 2) // 55296 B

__global__ void __launch_bounds__(256) attn_kernel()
{
    extern __shared__ __half smh[];
    const int tid  = threadIdx.x;
    const int warp = tid >> 5;
    const int lane = tid & 31;
    const int bh   = blockIdx.y;
    const int b    = bh / HEADS;
    const int h    = bh - b * HEADS;
    const int q0   = blockIdx.x * 128;

    const __half* Qg = g_Qh + (size_t)bh * SEQ * HDIM;
    const __half* Kg = g_Kh + (size_t)bh * SEQ * HDIM;
    const __half* Vg = g_Vh + (size_t)bh * SEQ * HDIM;

    uint32_t Qs_u = smem_u32(smh);
    uint32_t Ks_u = Qs_u + Q_TILE_H * 2;
    uint32_t Vs_u = Ks_u + 2 * KV_TILE_H * 2;

    auto issue_kv = [&](int kt, int st) {
        const int kbase = kt * 64;
        #pragma unroll
        for (int j = 0; j < 2; j++) {
            int i  = tid + j * 256;
            int r  = i >> 3;
            int c8 = (i & 7) << 3;
            int ki = kbase + r;
            bool p = ki < SEQ;
            uint32_t off = (uint32_t)(st * KV_TILE_H + r * LDH + c8) * 2;
            cp16(Ks_u + off, Kg + (size_t)ki * HDIM + c8, p);
            cp16(Vs_u + off, Vg + (size_t)ki * HDIM + c8, p);
        }
        CP_COMMIT();
    };

    #pragma unroll
    for (int j = 0; j < 4; j++) {
        int i  = tid + j * 256;
        int r  = i >> 3;
        int c8 = (i & 7) << 3;
        int qi = q0 + r;
        cp16(Qs_u + (uint32_t)(r * LDH + c8) * 2, Qg + (size_t)qi * HDIM + c8, qi < SEQ);
    }
    issue_kv(0, 0);

    CP_WAIT0();
    __syncthreads();

    uint32_t qa[4][4];
    {
        const int l8  = lane & 7;
        const int sel = lane >> 3;
        #pragma unroll
        for (int kk = 0; kk < 4; kk++) {
            uint32_t addr = Qs_u +
                (uint32_t)((warp * 16 + (sel & 1) * 8 + l8) * LDH + kk * 16 + (sel >> 1) * 8) * 2;
            ldsm_x4(qa[kk], addr);
        }
    }
    if (KV_TILES > 1) issue_kv(1, 1);

    float o[8][4];
    #pragma unroll
    for (int j = 0; j < 8; j++)
        #pragma unroll
        for (int c = 0; c < 4; c++) o[j][c] = 0.f;
    float mrow[2] = {-1e30f, -1e30f};
    float lrow[2] = {0.f, 0.f};

    const int l16 = lane & 15;

    for (int kt = 0; kt < KV_TILES; kt++) {
        const int st = kt & 1;
        if (kt > 0) {
            CP_WAIT0();
            __syncthreads();
            if (kt + 1 < KV_TILES) issue_kv(kt + 1, st ^ 1);
        }
        const uint32_t Kt_u = Ks_u + (uint32_t)(st * KV_TILE_H) * 2;
        const uint32_t Vt_u = Vs_u + (uint32_t)(st * KV_TILE_H) * 2;

        float s[8][4];
        #pragma unroll
        for (int j = 0; j < 8; j++)
            #pragma unroll
            for (int c = 0; c < 4; c++) s[j][c] = 0.f;

        #pragma unroll
        for (int kk = 0; kk < 4; kk++) {
            #pragma unroll
            for (int j = 0; j < 8; j++) {
                uint32_t b0, b1;
                uint32_t addr = Kt_u +
                    (uint32_t)((j * 8 + (l16 & 7)) * LDH + kk * 16 + (l16 >> 3) * 8) * 2;
                ldsm_x2(b0, b1, addr);
                mma16816(s[j], qa[kk], b0, b1);
            }
        }

        const int kvbase = kt * 64;
        const int kvc = kvbase + 2 * (lane & 3);
        float mx0 = mrow[0], mx1 = mrow[1];
        #pragma unroll
        for (int j = 0; j < 8; j++) {
            int kv = kvc + j * 8;
            if (kv     >= SEQ) { s[j][0] = -1e30f; s[j][2] = -1e30f; }
            if (kv + 1 >= SEQ) { s[j][1] = -1e30f; s[j][3] = -1e30f; }
            mx0 = fmaxf(mx0, fmaxf(s[j][0], s[j][1]));
            mx1 = fmaxf(mx1, fmaxf(s[j][2], s[j][3]));
        }
        mx0 = fmaxf(mx0, __shfl_xor_sync(0xffffffffu, mx0, 1));
        mx0 = fmaxf(mx0, __shfl_xor_sync(0xffffffffu, mx0, 2));
        mx1 = fmaxf(mx1, __shfl_xor_sync(0xffffffffu, mx1, 1));
        mx1 = fmaxf(mx1, __shfl_xor_sync(0xffffffffu, mx1, 2));

        const float alpha0 = __expf(mrow[0] - mx0);
        const float alpha1 = __expf(mrow[1] - mx1);
        mrow[0] = mx0; mrow[1] = mx1;

        float ls0 = 0.f, ls1 = 0.f;
        uint32_t pa[4][4];
        #pragma unroll
        for (int j = 0; j < 8; j++) {
            float p0 = __expf(s[j][0] - mx0);
            float p1 = __expf(s[j][1] - mx0);
            float p2 = __expf(s[j][2] - mx1);
            float p3 = __expf(s[j][3] - mx1);
            ls0 += p0 + p1;
            ls1 += p2 + p3;
            __half2 h01 = __floats2half2_rn(p0, p1);
            __half2 h23 = __floats2half2_rn(p2, p3);
            pa[j >> 1][(j & 1) * 2 + 0] = *(uint32_t*)&h01;
            pa[j >> 1][(j & 1) * 2 + 1] = *(uint32_t*)&h23;
        }
        ls0 += __shfl_xor_sync(0xffffffffu, ls0, 1);
        ls0 += __shfl_xor_sync(0xffffffffu, ls0, 2);
        ls1 += __shfl_xor_sync(0xffffffffu, ls1, 1);
        ls1 += __shfl_xor_sync(0xffffffffu, ls1, 2);
        lrow[0] = lrow[0] * alpha0 + ls0;
        lrow[1] = lrow[1] * alpha1 + ls1;

        #pragma unroll
        for (int j = 0; j < 8; j++) {
            o[j][0] *= alpha0; o[j][1] *= alpha0;
            o[j][2] *= alpha1; o[j][3] *= alpha1;
        }

        #pragma unroll
        for (int kk = 0; kk < 4; kk++) {
            #pragma unroll
            for (int j = 0; j < 8; j++) {
                uint32_t b0, b1;
                uint32_t addr = Vt_u + (uint32_t)((kk * 16 + l16) * LDH + j * 8) * 2;
                ldsm_x2t(b0, b1, addr);
                mma16816(o[j], pa[kk], b0, b1);
            }
        }
    }

    const float rinv0 = 1.0f / lrow[0];
    const float rinv1 = 1.0f / lrow[1];
    const int qi0 = q0 + warp * 16 + (lane >> 2);
    const int qi1 = qi0 + 8;
    const int dbase = h * HDIM + 2 * (lane & 3);
    #pragma unroll
    for (int j = 0; j < 8; j++) {
        int d = dbase + j * 8;
        if (qi0 < SEQ) {
            __half2 v = __floats2half2_rn(o[j][0] * rinv0, o[j][1] * rinv0);
            *(__half2*)(g_Oh + (size_t)(b * SEQ + qi0) * EMBED + d) = v;
        }
        if (qi1 < SEQ) {
            __half2 v = __floats2half2_rn(o[j][2] * rinv1, o[j][3] * rinv1);
            *(__half2*)(g_Oh + (size_t)(b * SEQ + qi1) * EMBED + d) = v;
        }
    }
}

// ===========================================================================
// Aux: single fused fp32 -> fp16 conversion over X, Wqkv, Wproj
// ===========================================================================
#define N8_X  ((size_t)MROWS * EMBED / 8)
#define N8_W1 ((size_t)EMBED * QKV_N / 8)
#define N8_W2 ((size_t)EMBED * EMBED / 8)

__global__ void f2h_all_kernel(const float* __restrict__ x,
                               const float* __restrict__ w1,
                               const float* __restrict__ w2)
{
    const size_t ntot = N8_X + N8_W1 + N8_W2;
    for (size_t i = blockIdx.x * blockDim.x + threadIdx.x; i < ntot;
         i += (size_t)gridDim.x * blockDim.x) {
        const float* src;
        __half* dst;
        size_t k;
        if (i < N8_X)             { src = x;  dst = g_Xh;     k = i; }
        else if (i < N8_X + N8_W1){ src = w1; dst = g_Wqkvh;  k = i - N8_X; }
        else                      { src = w2; dst = g_Wprojh; k = i - N8_X - N8_W1; }
        float4 a = ((const float4*)src)[2 * k];
        float4 b = ((const float4*)src)[2 * k + 1];
        __half2 h0 = __floats2half2_rn(a.x, a.y);
        __half2 h1 = __floats2half2_rn(a.z, a.w);
        __half2 h2 = __floats2half2_rn(b.x, b.y);
        __half2 h3 = __floats2half2_rn(b.z, b.w);
        uint4 o;
        o.x = *(uint32_t*)&h0; o.y = *(uint32_t*)&h1;
        o.z = *(uint32_t*)&h2; o.w = *(uint32_t*)&h3;
        ((uint4*)dst)[k] = o;
    }
}

// ===========================================================================
extern "C" void kernel_launch(void* const* d_in, const int* in_sizes, int n_in,
                              void* d_out, int out_size)
{
    (void)in_sizes; (void)n_in; (void)out_size;
    const float* x      = (const float*)d_in[0];
    const float* w_qkv  = (const float*)d_in[1];
    const float* w_proj = (const float*)d_in[2];
    const float* b_proj = (const float*)d_in[3];
    float* out = (float*)d_out;

    cudaFuncSetAttribute(gemm_qkv_kernel,  cudaFuncAttributeMaxDynamicSharedMemorySize, GEMM_SMEM_BYTES);
    cudaFuncSetAttribute(gemm_proj_kernel, cudaFuncAttributeMaxDynamicSharedMemorySize, GEMM_SMEM_BYTES);
    cudaFuncSetAttribute(attn_kernel,      cudaFuncAttributeMaxDynamicSharedMemorySize, (int)ATTN_SMEM);

    __half *dXh, *dWqkvh, *dWprojh, *dOh;
    cudaGetSymbolAddress((void**)&dXh,     g_Xh);
    cudaGetSymbolAddress((void**)&dWqkvh,  g_Wqkvh);
    cudaGetSymbolAddress((void**)&dWprojh, g_Wprojh);
    cudaGetSymbolAddress((void**)&dOh,     g_Oh);

    f2h_all_kernel<<<2048, 256>>>(x, w_qkv, w_proj);

    const int mblocks = (MROWS + BM - 1) / BM;   // 145
    gemm_qkv_kernel<<<dim3(QKV_N / BN, mblocks), 256, GEMM_SMEM_BYTES>>>(dXh, dWqkvh);

    const int qblocks = (SEQ + 127) / 128;       // 5
    attn_kernel<<<dim3(qblocks, BATCH * HEADS), 256, ATTN_SMEM>>>();

    gemm_proj_kernel<<<dim3(EMBED / BN, mblocks), 256, GEMM_SMEM_BYTES>>>(dOh, dWprojh, b_proj, out);
}

// round 11
// speedup vs baseline: 6.3480x; 1.0605x over previous
#include <cuda_runtime.h>
#include <cuda_fp16.h>
#include <cstdint>

#define BATCH   32
#define SEQ     577
#define EMBED   768
#define HEADS   12
#define HDIM    64
#define MROWS   (BATCH * SEQ)        // 18464
#define QKV_N   (3 * EMBED)          // 2304
// log2 domain: Q pre-scaled by ATT_SCALE * log2(e); softmax uses ex2.approx
#define ATT_SCALE_LOG2E 0.1803368801111204f

// ---------------- scratch (module-load allocated, no runtime allocs) -------
__device__ __half g_Qh[(size_t)BATCH * HEADS * SEQ * HDIM];   // [b,h,n,d], pre-scaled
__device__ __half g_Kh[(size_t)BATCH * HEADS * SEQ * HDIM];
__device__ __half g_Vh[(size_t)BATCH * HEADS * SEQ * HDIM];
__device__ __half g_Oh[(size_t)MROWS * EMBED];                // attention out (half)
__device__ __half g_Xh[(size_t)MROWS * EMBED];                // half X
__device__ __half g_Wqkvh[(size_t)EMBED * QKV_N];             // half W_qkv (row-major)
__device__ __half g_Wprojh[(size_t)EMBED * EMBED];            // half W_proj (row-major)

// ---------------- PTX helpers ----------------------------------------------
__device__ __forceinline__ uint32_t smem_u32(const void* p) {
    uint32_t a;
    asm("{ .reg .u64 t; cvta.to.shared.u64 t, %1; cvt.u32.u64 %0, t; }"
        : "=r"(a) : "l"(p));
    return a;
}
__device__ __forceinline__ void cp16(uint32_t dst, const void* src, bool pred) {
    int sz = pred ? 16 : 0;
    asm volatile("cp.async.cg.shared.global [%0], [%1], 16, %2;\n"
                 :: "r"(dst), "l"(src), "r"(sz));
}
#define CP_COMMIT() asm volatile("cp.async.commit_group;\n" ::: "memory")
#define CP_WAIT1()  asm volatile("cp.async.wait_group 1;\n" ::: "memory")
#define CP_WAIT0()  asm volatile("cp.async.wait_group 0;\n" ::: "memory")

__device__ __forceinline__ void ldsm_x4(uint32_t (&r)[4], uint32_t addr) {
    asm volatile("ldmatrix.sync.aligned.m8n8.x4.shared.b16 {%0,%1,%2,%3}, [%4];"
                 : "=r"(r[0]), "=r"(r[1]), "=r"(r[2]), "=r"(r[3]) : "r"(addr));
}
__device__ __forceinline__ void ldsm_x4t(uint32_t (&r)[4], uint32_t addr) {
    asm volatile("ldmatrix.sync.aligned.m8n8.x4.trans.shared.b16 {%0,%1,%2,%3}, [%4];"
                 : "=r"(r[0]), "=r"(r[1]), "=r"(r[2]), "=r"(r[3]) : "r"(addr));
}
__device__ __forceinline__ void mma16816(float (&d)[4], const uint32_t (&a)[4],
                                         uint32_t b0, uint32_t b1) {
    asm volatile("mma.sync.aligned.m16n8k16.row.col.f32.f16.f16.f32 "
                 "{%0,%1,%2,%3}, {%4,%5,%6,%7}, {%8,%9}, {%0,%1,%2,%3};"
                 : "+f"(d[0]), "+f"(d[1]), "+f"(d[2]), "+f"(d[3])
                 : "r"(a[0]), "r"(a[1]), "r"(a[2]), "r"(a[3]), "r"(b0), "r"(b1));
}
__device__ __forceinline__ float ex2(float x) {
    float r;
    asm("ex2.approx.ftz.f32 %0, %1;" : "=f"(r) : "f"(x));
    return r;
}

// ---------------- GEMM tiling (raw mma, fp16) -------------------------------
// BM=128, BN=128, BK=64; 8 warps as 2(m) x 4(n); warp tile 64x32.
// 3-stage pipeline, wait_group 1 + one __syncthreads per K-iteration.
#define BM 128
#define BN 128
#define BK 64
#define LDA 72
#define A_ST (BM * LDA)
#define B_ST_B 16384
#define KTILES (EMBED / BK)          // 12
#define GEMM_SMEM_BYTES (3 * (A_ST * 2 + B_ST_B))   // 104448

template <typename EPI>
__device__ __forceinline__ void gemm_mma(
    const __half* __restrict__ Ag, const __half* __restrict__ Bg, int ldb_g,
    int m0, int n0, bool mtail, EPI epi)
{
    extern __shared__ __half smh[];
    uint32_t sA_u = smem_u32(smh);
    uint32_t sB_u = sA_u + 3 * A_ST * 2;

    const int tid  = threadIdx.x;
    const int warp = tid >> 5;
    const int lane = tid & 31;
    const int wm   = warp >> 2;      // 0..1
    const int wn   = warp & 3;       // 0..3

    auto issue = [&](int kt, int st) {
        const int k0 = kt * BK;
        #pragma unroll
        for (int j = 0; j < 4; j++) {
            int i  = tid + j * 256;
            int r  = i >> 3;
            int ch = i & 7;
            int gm = m0 + r;
            bool p = !mtail || (gm < MROWS);
            cp16(sA_u + (uint32_t)(st * A_ST + r * LDA + ch * 8) * 2,
                 Ag + (size_t)gm * EMBED + k0 + ch * 8, p);
        }
        #pragma unroll
        for (int j = 0; j < 4; j++) {
            int i  = tid + j * 256;
            int r  = i >> 4;
            int c  = i & 15;
            cp16(sB_u + (uint32_t)(st * B_ST_B + r * 256 + ((c ^ (r & 7)) << 4)),
                 Bg + (size_t)(k0 + r) * ldb_g + n0 + c * 8, true);
        }
        CP_COMMIT();
    };

    float acc[4][4][4];
    #pragma unroll
    for (int i = 0; i < 4; i++)
        #pragma unroll
        for (int j = 0; j < 4; j++)
            #pragma unroll
            for (int c = 0; c < 4; c++) acc[i][j][c] = 0.f;

    issue(0, 0);
    issue(1, 1);

    const int l16 = lane & 15;
    const int lh  = lane >> 4;

    for (int it = 0; it < KTILES; it++) {
        if (it == KTILES - 1) CP_WAIT0(); else CP_WAIT1();
        __syncthreads();

        const int st = it % 3;
        const uint32_t aBase = sA_u + (uint32_t)(st * A_ST) * 2;
        const uint32_t bBase = sB_u + (uint32_t)(st * B_ST_B);

        // kk = 0: load fragments BEFORE issuing next tile's cp.async (the
        // volatile cp.async block otherwise fences ldsm below it).
        {
            uint32_t am[4][4];
            #pragma unroll
            for (int i = 0; i < 4; i++) {
                int row = wm * 64 + i * 16 + l16;
                ldsm_x4(am[i], aBase + (uint32_t)(row * LDA + lh * 8) * 2);
            }
            uint32_t bf[2][4];
            #pragma unroll
            for (int jj = 0; jj < 2; jj++) {
                int r = l16;
                int c = wn * 4 + jj * 2 + lh;
                ldsm_x4t(bf[jj], bBase + (uint32_t)(r * 256 + ((c ^ (r & 7)) << 4)));
            }
            if (it + 2 < KTILES) issue(it + 2, (it + 2) % 3);
            #pragma unroll
            for (int i = 0; i < 4; i++) {
                #pragma unroll
                for (int jj = 0; jj < 2; jj++) {
                    mma16816(acc[i][jj * 2 + 0], am[i], bf[jj][0], bf[jj][1]);
                    mma16816(acc[i][jj * 2 + 1], am[i], bf[jj][2], bf[jj][3]);
                }
            }
        }
        #pragma unroll
        for (int kk = 1; kk < 4; kk++) {
            uint32_t am[4][4];
            #pragma unroll
            for (int i = 0; i < 4; i++) {
                int row = wm * 64 + i * 16 + l16;
                ldsm_x4(am[i], aBase + (uint32_t)(row * LDA + kk * 16 + lh * 8) * 2);
            }
            uint32_t bf[2][4];
            #pragma unroll
            for (int jj = 0; jj < 2; jj++) {
                int r = kk * 16 + l16;
                int c = wn * 4 + jj * 2 + lh;
                ldsm_x4t(bf[jj], bBase + (uint32_t)(r * 256 + ((c ^ (r & 7)) << 4)));
            }
            #pragma unroll
            for (int i = 0; i < 4; i++) {
                #pragma unroll
                for (int jj = 0; jj < 2; jj++) {
                    mma16816(acc[i][jj * 2 + 0], am[i], bf[jj][0], bf[jj][1]);
                    mma16816(acc[i][jj * 2 + 1], am[i], bf[jj][2], bf[jj][3]);
                }
            }
        }
    }

    const int row0 = m0 + wm * 64 + (lane >> 2);
    const int gnb  = n0 + wn * 32 + 2 * (lane & 3);
    #pragma unroll
    for (int i = 0; i < 4; i++) {
        #pragma unroll
        for (int j = 0; j < 4; j++) {
            int gn = gnb + j * 8;
            epi(row0 + i * 16,     gn, acc[i][j][0], acc[i][j][1]);
            epi(row0 + i * 16 + 8, gn, acc[i][j][2], acc[i][j][3]);
        }
    }
}

// ===========================================================================
// Kernel 1: QKV GEMM + scatter epilogue (Q scaled by ATT_SCALE*log2e)
// ===========================================================================
__global__ void __launch_bounds__(256, 2) gemm_qkv_kernel(const __half* __restrict__ X,
                                                          const __half* __restrict__ W)
{
    const int m0 = blockIdx.y * BM;
    const int n0 = blockIdx.x * BN;
    const bool mtail = (m0 + BM > MROWS);

    gemm_mma(X, W, QKV_N, m0, n0, mtail,
        [&](int gm, int gn, float v0, float v1) {
            if (gm >= MROWS) return;
            int b   = gm / SEQ;
            int tok = gm - b * SEQ;
            int s   = gn / EMBED;
            int rem = gn - s * EMBED;
            int h   = rem >> 6;
            int d   = rem & 63;
            size_t idx = ((size_t)(b * HEADS + h) * SEQ + tok) * HDIM + d;
            if (s == 0) {
                *(__half2*)(g_Qh + idx) =
                    __floats2half2_rn(v0 * ATT_SCALE_LOG2E, v1 * ATT_SCALE_LOG2E);
            } else if (s == 1) {
                *(__half2*)(g_Kh + idx) = __floats2half2_rn(v0, v1);
            } else {
                *(__half2*)(g_Vh + idx) = __floats2half2_rn(v0, v1);
            }
        });
}

// ===========================================================================
// Kernel 3: projection GEMM.  out = g_Oh @ Wp + bias
// ===========================================================================
__global__ void __launch_bounds__(256, 2) gemm_proj_kernel(const __half* __restrict__ A,
                                                           const __half* __restrict__ W,
                                                           const float* __restrict__ bias,
                                                           float* __restrict__ out)
{
    const int m0 = blockIdx.y * BM;
    const int n0 = blockIdx.x * BN;
    const bool mtail = (m0 + BM > MROWS);

    gemm_mma(A, W, EMBED, m0, n0, mtail,
        [&](int gm, int gn, float v0, float v1) {
            if (gm >= MROWS) return;
            float2 v;
            v.x = v0 + bias[gn];
            v.y = v1 + bias[gn + 1];
            *(float2*)(out + (size_t)gm * EMBED + gn) = v;
        });
}

// ===========================================================================
// Kernel 2: flash attention, FA2-style; x4 ldsm batching, exp2-domain softmax
// ===========================================================================
#define KV_TILES ((SEQ + 63) / 64)                 // 10
#define LDH 72
#define KV_TILE_H (64 * LDH)
#define Q_TILE_H  (128 * LDH)
#define ATTN_SMEM ((Q_TILE_H + 4 * KV_TILE_H) * 2) // 55296 B

__global__ void __launch_bounds__(256) attn_kernel()
{
    extern __shared__ __half smh[];
    const int tid  = threadIdx.x;
    const int warp = tid >> 5;
    const int lane = tid & 31;
    const int bh   = blockIdx.y;
    const int b    = bh / HEADS;
    const int h    = bh - b * HEADS;
    const int q0   = blockIdx.x * 128;

    const __half* Qg = g_Qh + (size_t)bh * SEQ * HDIM;
    const __half* Kg = g_Kh + (size_t)bh * SEQ * HDIM;
    const __half* Vg = g_Vh + (size_t)bh * SEQ * HDIM;

    uint32_t Qs_u = smem_u32(smh);
    uint32_t Ks_u = Qs_u + Q_TILE_H * 2;
    uint32_t Vs_u = Ks_u + 2 * KV_TILE_H * 2;

    auto issue_kv = [&](int kt, int st) {
        const int kbase = kt * 64;
        #pragma unroll
        for (int j = 0; j < 2; j++) {
            int i  = tid + j * 256;
            int r  = i >> 3;
            int c8 = (i & 7) << 3;
            int ki = kbase + r;
            bool p = ki < SEQ;
            uint32_t off = (uint32_t)(st * KV_TILE_H + r * LDH + c8) * 2;
            cp16(Ks_u + off, Kg + (size_t)ki * HDIM + c8, p);
            cp16(Vs_u + off, Vg + (size_t)ki * HDIM + c8, p);
        }
        CP_COMMIT();
    };

    #pragma unroll
    for (int j = 0; j < 4; j++) {
        int i  = tid + j * 256;
        int r  = i >> 3;
        int c8 = (i & 7) << 3;
        int qi = q0 + r;
        cp16(Qs_u + (uint32_t)(r * LDH + c8) * 2, Qg + (size_t)qi * HDIM + c8, qi < SEQ);
    }
    issue_kv(0, 0);

    CP_WAIT0();
    __syncthreads();

    uint32_t qa[4][4];
    {
        const int l8  = lane & 7;
        const int sel = lane >> 3;
        #pragma unroll
        for (int kk = 0; kk < 4; kk++) {
            uint32_t addr = Qs_u +
                (uint32_t)((warp * 16 + (sel & 1) * 8 + l8) * LDH + kk * 16 + (sel >> 1) * 8) * 2;
            ldsm_x4(qa[kk], addr);
        }
    }
    if (KV_TILES > 1) issue_kv(1, 1);

    float o[8][4];
    #pragma unroll
    for (int j = 0; j < 8; j++)
        #pragma unroll
        for (int c = 0; c < 4; c++) o[j][c] = 0.f;
    float mrow[2] = {-1e30f, -1e30f};
    float lrow[2] = {0.f, 0.f};

    const int l8  = lane & 7;
    const int grp = lane >> 3;       // 0..3

    for (int kt = 0; kt < KV_TILES; kt++) {
        const int st = kt & 1;
        if (kt > 0) {
            CP_WAIT0();
            __syncthreads();
            if (kt + 1 < KV_TILES) issue_kv(kt + 1, st ^ 1);
        }
        const uint32_t Kt_u = Ks_u + (uint32_t)(st * KV_TILE_H) * 2;
        const uint32_t Vt_u = Vs_u + (uint32_t)(st * KV_TILE_H) * 2;

        // ---- S = Q @ K^T : x4 ldsm covers n8-tile pairs (j, j+1) ----------
        float s[8][4];
        #pragma unroll
        for (int j = 0; j < 8; j++)
            #pragma unroll
            for (int c = 0; c < 4; c++) s[j][c] = 0.f;

        #pragma unroll
        for (int kk = 0; kk < 4; kk++) {
            #pragma unroll
            for (int jp = 0; jp < 4; jp++) {
                // lanes 0-7 -> (j, half0); 8-15 -> (j, half1);
                // 16-23 -> (j+1, half0); 24-31 -> (j+1, half1)
                uint32_t bk[4];
                uint32_t addr = Kt_u +
                    (uint32_t)(((jp * 2 + (grp >> 1)) * 8 + l8) * LDH
                               + kk * 16 + (grp & 1) * 8) * 2;
                ldsm_x4(bk, addr);
                mma16816(s[jp * 2 + 0], qa[kk], bk[0], bk[1]);
                mma16816(s[jp * 2 + 1], qa[kk], bk[2], bk[3]);
            }
        }

        // ---- mask + online softmax in log2 domain -------------------------
        const int kvc = kt * 64 + 2 * (lane & 3);
        float mx0 = mrow[0], mx1 = mrow[1];
        #pragma unroll
        for (int j = 0; j < 8; j++) {
            int kv = kvc + j * 8;
            if (kv     >= SEQ) { s[j][0] = -1e30f; s[j][2] = -1e30f; }
            if (kv + 1 >= SEQ) { s[j][1] = -1e30f; s[j][3] = -1e30f; }
            mx0 = fmaxf(mx0, fmaxf(s[j][0], s[j][1]));
            mx1 = fmaxf(mx1, fmaxf(s[j][2], s[j][3]));
        }
        mx0 = fmaxf(mx0, __shfl_xor_sync(0xffffffffu, mx0, 1));
        mx0 = fmaxf(mx0, __shfl_xor_sync(0xffffffffu, mx0, 2));
        mx1 = fmaxf(mx1, __shfl_xor_sync(0xffffffffu, mx1, 1));
        mx1 = fmaxf(mx1, __shfl_xor_sync(0xffffffffu, mx1, 2));

        const float alpha0 = ex2(mrow[0] - mx0);
        const float alpha1 = ex2(mrow[1] - mx1);
        mrow[0] = mx0; mrow[1] = mx1;

        float ls0 = 0.f, ls1 = 0.f;
        uint32_t pa[4][4];
        #pragma unroll
        for (int j = 0; j < 8; j++) {
            float p0 = ex2(s[j][0] - mx0);
            float p1 = ex2(s[j][1] - mx0);
            float p2 = ex2(s[j][2] - mx1);
            float p3 = ex2(s[j][3] - mx1);
            ls0 += p0 + p1;
            ls1 += p2 + p3;
            __half2 h01 = __floats2half2_rn(p0, p1);
            __half2 h23 = __floats2half2_rn(p2, p3);
            pa[j >> 1][(j & 1) * 2 + 0] = *(uint32_t*)&h01;
            pa[j >> 1][(j & 1) * 2 + 1] = *(uint32_t*)&h23;
        }
        ls0 += __shfl_xor_sync(0xffffffffu, ls0, 1);
        ls0 += __shfl_xor_sync(0xffffffffu, ls0, 2);
        ls1 += __shfl_xor_sync(0xffffffffu, ls1, 1);
        ls1 += __shfl_xor_sync(0xffffffffu, ls1, 2);
        lrow[0] = lrow[0] * alpha0 + ls0;
        lrow[1] = lrow[1] * alpha1 + ls1;

        #pragma unroll
        for (int j = 0; j < 8; j++) {
            o[j][0] *= alpha0; o[j][1] *= alpha0;
            o[j][2] *= alpha1; o[j][3] *= alpha1;
        }

        // ---- O += P @ V : x4t ldsm covers n8-tile pairs --------------------
        #pragma unroll
        for (int kk = 0; kk < 4; kk++) {
            #pragma unroll
            for (int jp = 0; jp < 4; jp++) {
                // lanes 0-7 -> rows kk*16+l8, col j; 8-15 -> rows +8, col j;
                // 16-23 -> rows kk*16+l8, col j+1; 24-31 -> rows +8, col j+1
                uint32_t bv[4];
                uint32_t addr = Vt_u +
                    (uint32_t)((kk * 16 + (grp & 1) * 8 + l8) * LDH
                               + (jp * 2 + (grp >> 1)) * 8) * 2;
                ldsm_x4t(bv, addr);
                mma16816(o[jp * 2 + 0], pa[kk], bv[0], bv[1]);
                mma16816(o[jp * 2 + 1], pa[kk], bv[2], bv[3]);
            }
        }
    }

    const float rinv0 = 1.0f / lrow[0];
    const float rinv1 = 1.0f / lrow[1];
    const int qi0 = q0 + warp * 16 + (lane >> 2);
    const int qi1 = qi0 + 8;
    const int dbase = h * HDIM + 2 * (lane & 3);
    #pragma unroll
    for (int j = 0; j < 8; j++) {
        int d = dbase + j * 8;
        if (qi0 < SEQ) {
            __half2 v = __floats2half2_rn(o[j][0] * rinv0, o[j][1] * rinv0);
            *(__half2*)(g_Oh + (size_t)(b * SEQ + qi0) * EMBED + d) = v;
        }
        if (qi1 < SEQ) {
            __half2 v = __floats2half2_rn(o[j][2] * rinv1, o[j][3] * rinv1);
            *(__half2*)(g_Oh + (size_t)(b * SEQ + qi1) * EMBED + d) = v;
        }
    }
}

// ===========================================================================
// Aux: single fused fp32 -> fp16 conversion over X, Wqkv, Wproj
// ===========================================================================
#define N8_X  ((size_t)MROWS * EMBED / 8)
#define N8_W1 ((size_t)EMBED * QKV_N / 8)
#define N8_W2 ((size_t)EMBED * EMBED / 8)

__global__ void f2h_all_kernel(const float* __restrict__ x,
                               const float* __restrict__ w1,
                               const float* __restrict__ w2)
{
    const size_t ntot = N8_X + N8_W1 + N8_W2;
    for (size_t i = blockIdx.x * blockDim.x + threadIdx.x; i < ntot;
         i += (size_t)gridDim.x * blockDim.x) {
        const float* src;
        __half* dst;
        size_t k;
        if (i < N8_X)             { src = x;  dst = g_Xh;     k = i; }
        else if (i < N8_X + N8_W1){ src = w1; dst = g_Wqkvh;  k = i - N8_X; }
        else                      { src = w2; dst = g_Wprojh; k = i - N8_X - N8_W1; }
        float4 a = ((const float4*)src)[2 * k];
        float4 b = ((const float4*)src)[2 * k + 1];
        __half2 h0 = __floats2half2_rn(a.x, a.y);
        __half2 h1 = __floats2half2_rn(a.z, a.w);
        __half2 h2 = __floats2half2_rn(b.x, b.y);
        __half2 h3 = __floats2half2_rn(b.z, b.w);
        uint4 o;
        o.x = *(uint32_t*)&h0; o.y = *(uint32_t*)&h1;
        o.z = *(uint32_t*)&h2; o.w = *(uint32_t*)&h3;
        ((uint4*)dst)[k] = o;
    }
}

// ===========================================================================
extern "C" void kernel_launch(void* const* d_in, const int* in_sizes, int n_in,
                              void* d_out, int out_size)
{
    (void)in_sizes; (void)n_in; (void)out_size;
    const float* x      = (const float*)d_in[0];
    const float* w_qkv  = (const float*)d_in[1];
    const float* w_proj = (const float*)d_in[2];
    const float* b_proj = (const float*)d_in[3];
    float* out = (float*)d_out;

    cudaFuncSetAttribute(gemm_qkv_kernel,  cudaFuncAttributeMaxDynamicSharedMemorySize, GEMM_SMEM_BYTES);
    cudaFuncSetAttribute(gemm_proj_kernel, cudaFuncAttributeMaxDynamicSharedMemorySize, GEMM_SMEM_BYTES);
    cudaFuncSetAttribute(attn_kernel,      cudaFuncAttributeMaxDynamicSharedMemorySize, (int)ATTN_SMEM);

    __half *dXh, *dWqkvh, *dWprojh, *dOh;
    cudaGetSymbolAddress((void**)&dXh,     g_Xh);
    cudaGetSymbolAddress((void**)&dWqkvh,  g_Wqkvh);
    cudaGetSymbolAddress((void**)&dWprojh, g_Wprojh);
    cudaGetSymbolAddress((void**)&dOh,     g_Oh);

    f2h_all_kernel<<<2048, 256>>>(x, w_qkv, w_proj);

    const int mblocks = (MROWS + BM - 1) / BM;   // 145
    gemm_qkv_kernel<<<dim3(QKV_N / BN, mblocks), 256, GEMM_SMEM_BYTES>>>(dXh, dWqkvh);

    const int qblocks = (SEQ + 127) / 128;       // 5
    attn_kernel<<<dim3(qblocks, BATCH * HEADS), 256, ATTN_SMEM>>>();

    gemm_proj_kernel<<<dim3(EMBED / BN, mblocks), 256, GEMM_SMEM_BYTES>>>(dOh, dWprojh, b_proj, out);
}